// round 1
// baseline (speedup 1.0000x reference)
#include <cuda_runtime.h>
#include <math.h>

#define BB 2
#define TT 6
#define PP 20480
#define DIMX 96
#define DIN 128
#define DPROJ 266
#define NTOK (BB*TT*PP)      /* 245760 */
#define NHEADS 8
#define LSEQ 30

// ---------------- scratch (static device allocations; no cudaMalloc) ----------------
__device__ float S_xn[(size_t)NTOK*DIN];    // 126 MB
__device__ float S_u [(size_t)NTOK*DPROJ];  // 261 MB
__device__ float S_yf[(size_t)NTOK*DIN];    // 126 MB
__device__ float S_yb[(size_t)NTOK*DIN];    // 126 MB
__device__ float S_x1[(size_t)NTOK*DIMX];   // 94 MB
__device__ float S_tt[(size_t)NTOK*DIMX];   // 94 MB

__device__ __forceinline__ float geluf(float v) {
    return 0.5f * v * (1.0f + erff(v * 0.70710678118654752f));
}

// ================= K0: gather + embed + LN + loan1 -> xn =================
// block = 128 threads, handles 8 tokens sequentially
__global__ void k0_prologue(const float* __restrict__ x,
                            const float* __restrict__ xstat,
                            const float* __restrict__ xhres,
                            const int*   __restrict__ curves,
                            const float* __restrict__ embed_w,
                            const float* __restrict__ embed_b,
                            const float* __restrict__ loan1_w,
                            const float* __restrict__ loan1_b)
{
    const int tid = threadIdx.x;
    __shared__ float shh[28];
    __shared__ float shs[8];
    __shared__ float r1[4], r2[4];

    for (int it = 0; it < 8; it++) {
        const int tok = blockIdx.x * 8 + it;
        const int b  = tok / (TT*PP);
        const int tp = tok - b*TT*PP;
        const int t  = tp / PP;
        const int p  = tp - t*PP;
        const int g  = curves[b*PP + p];
        const size_t base = (size_t)(b*TT + t)*PP + g;

        __syncthreads();
        if (tid < 28) shh[tid] = xhres[base*28 + tid];
        if (tid < 8)  shs[tid] = xstat[base*8 + tid];
        __syncthreads();

        float v;
        if (tid < 96) {
            v = x[base*96 + tid];
        } else {
            int j = tid - 96;
            float a = embed_b[j];
            #pragma unroll
            for (int k = 0; k < 28; k++) a = fmaf(shh[k], embed_w[k*32 + j], a);
            v = tanhf(a);
        }
        float s1 = v, s2 = v*v;
        #pragma unroll
        for (int o = 16; o > 0; o >>= 1) {
            s1 += __shfl_xor_sync(0xffffffffu, s1, o);
            s2 += __shfl_xor_sync(0xffffffffu, s2, o);
        }
        if ((tid & 31) == 0) { r1[tid>>5] = s1; r2[tid>>5] = s2; }
        __syncthreads();
        s1 = r1[0]+r1[1]+r1[2]+r1[3];
        s2 = r2[0]+r2[1]+r2[2]+r2[3];
        float mu  = s1 * (1.0f/128.0f);
        float var = s2 * (1.0f/128.0f) - mu*mu;
        float rs  = rsqrtf(var + 1e-5f);
        float a = loan1_b[tid];
        #pragma unroll
        for (int k = 0; k < 8; k++) a = fmaf(shs[k], loan1_w[k*128 + tid], a);
        S_xn[(size_t)tok*DIN + tid] = (v - mu)*rs + tanhf(a);
    }
}

// ================= K1: in_proj SGEMM  u = xn @ W (128 x 266) =================
// BM=64, BN=64, K=128, 256 threads, 4x4 per thread
__global__ void k1_inproj(const float* __restrict__ W)
{
    extern __shared__ float sm1[];
    float* As = sm1;               // [64][132]
    float* Ws = sm1 + 64*132;      // [128][64]
    const int tid = threadIdx.x;
    const int m_base = blockIdx.x * 64;
    const int n_base = blockIdx.y * 64;

    for (int i = tid; i < 64*32; i += 256) {
        int m = i >> 5, k4 = i & 31;
        float4 v = *(const float4*)(S_xn + (size_t)(m_base+m)*128 + k4*4);
        *(float4*)(As + m*132 + k4*4) = v;
    }
    for (int i = tid; i < 128*64; i += 256) {
        int k = i >> 6, n = i & 63;
        int gn = n_base + n;
        Ws[k*64 + n] = (gn < DPROJ) ? W[(size_t)k*DPROJ + gn] : 0.0f;
    }
    __syncthreads();

    const int tx = tid & 15, ty = tid >> 4;
    const int m0 = ty*4, n0 = tx*4;
    float acc[4][4] = {};
    #pragma unroll 4
    for (int k = 0; k < 128; k++) {
        float4 bv = *(float4*)(Ws + k*64 + n0);
        #pragma unroll
        for (int j = 0; j < 4; j++) {
            float a = As[(m0+j)*132 + k];
            acc[j][0] = fmaf(a, bv.x, acc[j][0]);
            acc[j][1] = fmaf(a, bv.y, acc[j][1]);
            acc[j][2] = fmaf(a, bv.z, acc[j][2]);
            acc[j][3] = fmaf(a, bv.w, acc[j][3]);
        }
    }
    #pragma unroll
    for (int j = 0; j < 4; j++) {
        size_t row = (size_t)(m_base + m0 + j) * DPROJ;
        #pragma unroll
        for (int i2 = 0; i2 < 4; i2++) {
            int gn = n_base + n0 + i2;
            if (gn < DPROJ) S_u[row + gn] = acc[j][i2];
        }
    }
}

// ================= K2: mamba per-sequence (fwd+bwd) =================
// 16384 blocks (dir = blk>>13), 128 threads
__global__ void k2_mamba(
    const float* __restrict__ cw_f, const float* __restrict__ cb_f,
    const float* __restrict__ dtb_f, const float* __restrict__ al_f,
    const float* __restrict__ Dp_f, const float* __restrict__ nw_f,
    const float* __restrict__ cw_b, const float* __restrict__ cb_b,
    const float* __restrict__ dtb_b, const float* __restrict__ al_b,
    const float* __restrict__ Dp_b, const float* __restrict__ nw_b)
{
    extern __shared__ float sm2[];
    float* u_s  = sm2;                 // [30][268]
    float* xc_s = u_s + 30*268;        // [30][132]
    float* dt_s = xc_s + 30*132;       // [30][8]
    float* dA_s = dt_s + 240;          // [30][8]
    float* y_s  = dA_s + 240;          // [30][128]
    __shared__ float Aneg[8];

    const int blk = blockIdx.x;
    const int dir = blk >> 13;
    const int s   = blk & 8191;
    const int b   = s >> 12;
    const int sb  = s & 4095;
    const int tg  = sb >> 11;
    const int qg  = sb & 2047;
    const int tid = threadIdx.x;

    const float* conv_w = dir ? cw_b : cw_f;
    const float* conv_b = dir ? cb_b : cb_f;
    const float* dtb    = dir ? dtb_b : dtb_f;
    const float* alog   = dir ? al_b  : al_f;
    const float* Dp     = dir ? Dp_b  : Dp_f;
    const float* nw     = dir ? nw_b  : nw_f;
    float* ybuf         = dir ? S_yb  : S_yf;

    // load u for 30 sequence tokens (backward reads p flipped)
    for (int l = 0; l < 30; l++) {
        int l10  = l / 10;
        int t_in = tg*3 + l10;
        int p0   = qg*10 + (l - l10*10);
        int p_in = dir ? (PP-1-p0) : p0;
        const float2* src = (const float2*)(S_u + ((size_t)(b*TT + t_in)*PP + p_in)*DPROJ);
        float2* dst = (float2*)(u_s + l*268);
        for (int i = tid; i < 133; i += 128) dst[i] = src[i];
    }
    if (tid < 8) Aneg[tid] = -expf(alog[tid]);
    __syncthreads();

    // dt = softplus(raw + bias), dA = exp(dt*A)
    for (int i = tid; i < 240; i += 128) {
        int l = i >> 3, h = i & 7;
        float raw = u_s[l*268 + 258 + h] + dtb[h];
        float dt = (raw > 20.f) ? raw : log1pf(expf(raw));
        dt_s[l*8 + h] = dt;
        dA_s[l*8 + h] = expf(dt * Aneg[h]);
    }
    // causal depthwise conv (K=3) + silu over 130 channels
    for (int c = tid; c < 130; c += 128) {
        float w0 = conv_w[c*3+0], w1 = conv_w[c*3+1], w2 = conv_w[c*3+2];
        float bias = conv_b[c];
        float p2 = 0.f, p1 = 0.f;
        #pragma unroll
        for (int l = 0; l < 30; l++) {
            float v = u_s[l*268 + 128 + c];
            float a = fmaf(p2, w0, fmaf(p1, w1, fmaf(v, w2, bias)));
            xc_s[l*132 + c] = a / (1.f + expf(-a));
            p2 = p1; p1 = v;
        }
    }
    __syncthreads();

    // scan: thread c owns channel c (head = c>>4). D_STATE=1 -> scalar recurrence.
    {
        const int c = tid, h = c >> 4;
        const float Dh = Dp[h];
        float hs = 0.f;
        #pragma unroll
        for (int l = 0; l < 30; l++) {
            float xv = xc_s[l*132 + c];
            float Bv = xc_s[l*132 + 128];
            float Cv = xc_s[l*132 + 129];
            hs = fmaf(hs, dA_s[l*8+h], dt_s[l*8+h]*xv*Bv);
            float y = fmaf(hs, Cv, xv*Dh);
            float z = u_s[l*268 + c];
            y *= z / (1.f + expf(-z));
            y_s[l*128 + c] = y;
        }
    }
    __syncthreads();

    // per-token RMS norm, *norm_w, *0.5, scatter-write to _wrev position
    const int warp = tid >> 5, lane = tid & 31;
    const int abase = (tg*1024 + (qg>>1))*6 + (qg&1);
    for (int l = warp; l < 30; l += 4) {
        float4 v = *(float4*)(y_s + l*128 + lane*4);
        float ss = v.x*v.x + v.y*v.y + v.z*v.z + v.w*v.w;
        #pragma unroll
        for (int o = 16; o > 0; o >>= 1) ss += __shfl_xor_sync(0xffffffffu, ss, o);
        float scale = rsqrtf(ss*(1.f/128.f) + 1e-5f) * 0.5f;
        int l3 = l / 3;
        int f = l3*12288 + abase + (l - l3*3)*2;
        int t_out = f / PP;
        int p_out = f - t_out*PP;
        if (dir) p_out = PP-1 - p_out;
        float4 w = *(const float4*)(nw + lane*4);
        float4 o;
        o.x = v.x*scale*w.x; o.y = v.y*scale*w.y;
        o.z = v.z*scale*w.z; o.w = v.w*scale*w.w;
        *(float4*)(ybuf + ((size_t)(b*TT + t_out)*PP + p_out)*128 + lane*4) = o;
    }
}

// ================= K3: x1 = xg + (yf+yb) @ out_proj ; LN + loan2 -> tt =================
// BM=64, BN=96(full), K=128, 384 threads, 4x4 per thread
__global__ void k3_outproj(const float* __restrict__ Wo,
                           const float* __restrict__ x,
                           const int*   __restrict__ curves,
                           const float* __restrict__ xstat,
                           const float* __restrict__ loan2_w,
                           const float* __restrict__ loan2_b)
{
    extern __shared__ float sm3[];
    float* As  = sm3;              // [64][132]  (later overlaid by x1s [64][100])
    float* Ws  = sm3 + 64*132;     // [128][96]
    float* x1s = sm3;
    const int tid = threadIdx.x;   // 384
    const int m_base = blockIdx.x * 64;

    for (int i = tid; i < 64*32; i += 384) {
        int m = i >> 5, k4 = i & 31;
        size_t off = (size_t)(m_base+m)*128 + k4*4;
        float4 a  = *(const float4*)(S_yf + off);
        float4 bq = *(const float4*)(S_yb + off);
        a.x += bq.x; a.y += bq.y; a.z += bq.z; a.w += bq.w;
        *(float4*)(As + m*132 + k4*4) = a;
    }
    for (int i = tid; i < 128*96; i += 384) Ws[i] = Wo[i];
    __syncthreads();

    const int tx = tid % 24, ty = tid / 24;  // ty 0..15
    const int m0 = ty*4, n0 = tx*4;
    float acc[4][4] = {};
    #pragma unroll 4
    for (int k = 0; k < 128; k++) {
        float4 bv = *(float4*)(Ws + k*96 + n0);
        #pragma unroll
        for (int j = 0; j < 4; j++) {
            float a = As[(m0+j)*132 + k];
            acc[j][0] = fmaf(a, bv.x, acc[j][0]);
            acc[j][1] = fmaf(a, bv.y, acc[j][1]);
            acc[j][2] = fmaf(a, bv.z, acc[j][2]);
            acc[j][3] = fmaf(a, bv.w, acc[j][3]);
        }
    }
    __syncthreads();  // all As reads done -> safe to overlay x1s

    #pragma unroll
    for (int j = 0; j < 4; j++) {
        int gm = m_base + m0 + j;
        int b  = gm / (TT*PP);
        int tp = gm - b*TT*PP;
        int t  = tp / PP;
        int p  = tp - t*PP;
        int g  = curves[b*PP + p];
        float4 xv = *(const float4*)(x + ((size_t)(b*TT + t)*PP + g)*96 + n0);
        float4 o;
        o.x = acc[j][0] + xv.x; o.y = acc[j][1] + xv.y;
        o.z = acc[j][2] + xv.z; o.w = acc[j][3] + xv.w;
        *(float4*)(x1s + (m0+j)*100 + n0) = o;
        *(float4*)(S_x1 + (size_t)gm*96 + n0) = o;
    }
    __syncthreads();

    // per-row LN(96) + tanh(xs@loan2) -> tt
    const int warp = tid >> 5, lane = tid & 31;  // 12 warps
    for (int r = warp; r < 64; r += 12) {
        float v0 = x1s[r*100 + lane*3 + 0];
        float v1 = x1s[r*100 + lane*3 + 1];
        float v2 = x1s[r*100 + lane*3 + 2];
        float s1 = v0+v1+v2, s2 = v0*v0+v1*v1+v2*v2;
        #pragma unroll
        for (int o = 16; o > 0; o >>= 1) {
            s1 += __shfl_xor_sync(0xffffffffu, s1, o);
            s2 += __shfl_xor_sync(0xffffffffu, s2, o);
        }
        float mu  = s1 * (1.0f/96.0f);
        float var = s2 * (1.0f/96.0f) - mu*mu;
        float rs  = rsqrtf(var + 1e-5f);
        int gm = m_base + r;
        int b  = gm / (TT*PP);
        int tp = gm - b*TT*PP;
        int t  = tp / PP;
        int p  = tp - t*PP;
        int g  = curves[b*PP + p];
        size_t sbase = ((size_t)(b*TT + t)*PP + g)*8;
        float xs[8];
        #pragma unroll
        for (int k = 0; k < 8; k++) xs[k] = xstat[sbase + k];
        #pragma unroll
        for (int i2 = 0; i2 < 3; i2++) {
            int jj = lane*3 + i2;
            float a = loan2_b[jj];
            #pragma unroll
            for (int k = 0; k < 8; k++) a = fmaf(xs[k], loan2_w[k*96 + jj], a);
            float vv = (i2 == 0) ? v0 : ((i2 == 1) ? v1 : v2);
            S_tt[(size_t)gm*96 + jj] = (vv - mu)*rs + tanhf(a);
        }
    }
}

// ================= K4: out = x1 + gelu(tt@W1+b1)@W2 + b2 =================
// BM=64, 384 threads, both GEMMs fused with h in smem
__global__ void k4_mlp(const float* __restrict__ W1, const float* __restrict__ b1,
                       const float* __restrict__ W2, const float* __restrict__ b2,
                       float* __restrict__ out)
{
    extern __shared__ float sm4[];
    float* W1s = sm4;              // 96*96
    float* W2s = W1s + 96*96;      // 96*96
    float* tts = W2s + 96*96;      // [64][100]
    float* hs  = tts + 64*100;     // [64][100]
    const int tid = threadIdx.x;   // 384
    const int m_base = blockIdx.x * 64;

    for (int i = tid; i < 96*96; i += 384) { W1s[i] = W1[i]; W2s[i] = W2[i]; }
    for (int i = tid; i < 64*24; i += 384) {
        int m = i / 24, k4 = i - (i/24)*24;
        float4 v = *(const float4*)(S_tt + (size_t)(m_base+m)*96 + k4*4);
        *(float4*)(tts + m*100 + k4*4) = v;
    }
    __syncthreads();

    const int tx = tid % 24, ty = tid / 24;
    const int m0 = ty*4, n0 = tx*4;

    float acc[4][4] = {};
    #pragma unroll 4
    for (int k = 0; k < 96; k++) {
        float4 bv = *(float4*)(W1s + k*96 + n0);
        #pragma unroll
        for (int j = 0; j < 4; j++) {
            float a = tts[(m0+j)*100 + k];
            acc[j][0] = fmaf(a, bv.x, acc[j][0]);
            acc[j][1] = fmaf(a, bv.y, acc[j][1]);
            acc[j][2] = fmaf(a, bv.z, acc[j][2]);
            acc[j][3] = fmaf(a, bv.w, acc[j][3]);
        }
    }
    {
        float bb0 = b1[n0+0], bb1 = b1[n0+1], bb2 = b1[n0+2], bb3 = b1[n0+3];
        #pragma unroll
        for (int j = 0; j < 4; j++) {
            float4 o;
            o.x = geluf(acc[j][0] + bb0);
            o.y = geluf(acc[j][1] + bb1);
            o.z = geluf(acc[j][2] + bb2);
            o.w = geluf(acc[j][3] + bb3);
            *(float4*)(hs + (m0+j)*100 + n0) = o;
        }
    }
    __syncthreads();

    float ac2[4][4] = {};
    #pragma unroll 4
    for (int k = 0; k < 96; k++) {
        float4 bv = *(float4*)(W2s + k*96 + n0);
        #pragma unroll
        for (int j = 0; j < 4; j++) {
            float a = hs[(m0+j)*100 + k];
            ac2[j][0] = fmaf(a, bv.x, ac2[j][0]);
            ac2[j][1] = fmaf(a, bv.y, ac2[j][1]);
            ac2[j][2] = fmaf(a, bv.z, ac2[j][2]);
            ac2[j][3] = fmaf(a, bv.w, ac2[j][3]);
        }
    }
    {
        float bb0 = b2[n0+0], bb1 = b2[n0+1], bb2 = b2[n0+2], bb3 = b2[n0+3];
        #pragma unroll
        for (int j = 0; j < 4; j++) {
            size_t row = (size_t)(m_base + m0 + j) * 96;
            float4 xv = *(const float4*)(S_x1 + row + n0);
            float4 o;
            o.x = ac2[j][0] + bb0 + xv.x;
            o.y = ac2[j][1] + bb1 + xv.y;
            o.z = ac2[j][2] + bb2 + xv.z;
            o.w = ac2[j][3] + bb3 + xv.w;
            *(float4*)(out + row + n0) = o;
        }
    }
}

// ================= launcher =================
extern "C" void kernel_launch(void* const* d_in, const int* in_sizes, int n_in,
                              void* d_out, int out_size)
{
    const float* x       = (const float*)d_in[0];
    const float* xstat   = (const float*)d_in[1];
    const float* xhres   = (const float*)d_in[2];
    const int*   curves  = (const int*)  d_in[3];
    const float* embed_w = (const float*)d_in[4];
    const float* embed_b = (const float*)d_in[5];
    const float* loan1_w = (const float*)d_in[6];
    const float* loan1_b = (const float*)d_in[7];
    const float* loan2_w = (const float*)d_in[8];
    const float* loan2_b = (const float*)d_in[9];
    const float* in_proj = (const float*)d_in[10];
    const float* cw_f  = (const float*)d_in[11];
    const float* cb_f  = (const float*)d_in[12];
    const float* dtb_f = (const float*)d_in[13];
    const float* al_f  = (const float*)d_in[14];
    const float* Dp_f  = (const float*)d_in[15];
    const float* nw_f  = (const float*)d_in[16];
    const float* cw_b  = (const float*)d_in[17];
    const float* cb_b  = (const float*)d_in[18];
    const float* dtb_b = (const float*)d_in[19];
    const float* al_b  = (const float*)d_in[20];
    const float* Dp_b  = (const float*)d_in[21];
    const float* nw_b  = (const float*)d_in[22];
    const float* Wo    = (const float*)d_in[23];
    const float* W1    = (const float*)d_in[24];
    const float* b1    = (const float*)d_in[25];
    const float* W2    = (const float*)d_in[26];
    const float* b2    = (const float*)d_in[27];
    float* out = (float*)d_out;

    const int smem1 = (64*132 + 128*64) * 4;                    // 66560
    const int smem2 = (30*268 + 30*132 + 240 + 240 + 30*128)*4; // 65280
    const int smem3 = (64*132 + 128*96) * 4;                    // 82944
    const int smem4 = (96*96*2 + 64*100*2) * 4;                 // 124928

    cudaFuncSetAttribute(k1_inproj, cudaFuncAttributeMaxDynamicSharedMemorySize, smem1);
    cudaFuncSetAttribute(k2_mamba,  cudaFuncAttributeMaxDynamicSharedMemorySize, smem2);
    cudaFuncSetAttribute(k3_outproj,cudaFuncAttributeMaxDynamicSharedMemorySize, smem3);
    cudaFuncSetAttribute(k4_mlp,    cudaFuncAttributeMaxDynamicSharedMemorySize, smem4);

    k0_prologue<<<NTOK/8, 128>>>(x, xstat, xhres, curves, embed_w, embed_b, loan1_w, loan1_b);

    dim3 g1(NTOK/64, 5);
    k1_inproj<<<g1, 256, smem1>>>(in_proj);

    k2_mamba<<<16384, 128, smem2>>>(cw_f, cb_f, dtb_f, al_f, Dp_f, nw_f,
                                    cw_b, cb_b, dtb_b, al_b, Dp_b, nw_b);

    k3_outproj<<<NTOK/64, 384, smem3>>>(Wo, x, curves, xstat, loan2_w, loan2_b);

    k4_mlp<<<NTOK/64, 384, smem4>>>(W1, b1, W2, b2, out);
}

// round 2
// speedup vs baseline: 1.0077x; 1.0077x over previous
#include <cuda_runtime.h>
#include <math.h>

#define BB 2
#define TT 6
#define PP 20480
#define DIMX 96
#define DIN 128
#define DPROJ 266
#define NTOK (BB*TT*PP)      /* 245760 */
#define NHEADS 8
#define LSEQ 30

// ---------------- scratch (static device allocations; no cudaMalloc) ----------------
__device__ float S_xn[(size_t)NTOK*DIN];    // 126 MB
__device__ float S_u [(size_t)NTOK*DPROJ];  // 261 MB (reused as gelu scratch in k4)
__device__ float S_yf[(size_t)NTOK*DIN];    // 126 MB
__device__ float S_yb[(size_t)NTOK*DIN];    // 126 MB
__device__ float S_x1[(size_t)NTOK*DIMX];   // 94 MB
__device__ float S_tt[(size_t)NTOK*DIMX];   // 94 MB

__device__ __forceinline__ float geluf(float v) {
    return 0.5f * v * (1.0f + erff(v * 0.70710678118654752f));
}

__device__ __forceinline__ unsigned f2tf32(float f) {
    unsigned r;
    asm("cvt.rna.tf32.f32 %0, %1;" : "=r"(r) : "f"(f));
    return r;
}

// m16n8k8 tf32 MMA, fp32 accumulate, A row-major, B col-major
__device__ __forceinline__ void mma_tf32(float* c, const unsigned* a, const unsigned* b) {
    asm volatile(
        "mma.sync.aligned.m16n8k8.row.col.f32.tf32.tf32.f32 "
        "{%0,%1,%2,%3}, {%4,%5,%6,%7}, {%8,%9}, {%0,%1,%2,%3};"
        : "+f"(c[0]), "+f"(c[1]), "+f"(c[2]), "+f"(c[3])
        : "r"(a[0]), "r"(a[1]), "r"(a[2]), "r"(a[3]), "r"(b[0]), "r"(b[1]));
}

// ================= K0: gather + embed + LN + loan1 -> xn =================
// 512 threads = 4 parallel groups of 128 (one token each), 2 serial iterations
__global__ void k0_prologue(const float* __restrict__ x,
                            const float* __restrict__ xstat,
                            const float* __restrict__ xhres,
                            const int*   __restrict__ curves,
                            const float* __restrict__ embed_w,
                            const float* __restrict__ embed_b,
                            const float* __restrict__ loan1_w,
                            const float* __restrict__ loan1_b)
{
    const int tid = threadIdx.x;
    const int grp = tid >> 7;      // 0..3
    const int lt  = tid & 127;     // 0..127
    __shared__ float shh[4][28];
    __shared__ float shs[4][8];
    __shared__ float r1[4][4], r2[4][4];

    for (int it = 0; it < 2; it++) {
        const int tok = blockIdx.x * 8 + it * 4 + grp;
        const int b  = tok / (TT*PP);
        const int tp = tok - b*TT*PP;
        const int t  = tp / PP;
        const int p  = tp - t*PP;
        const int g  = curves[b*PP + p];
        const size_t base = (size_t)(b*TT + t)*PP + g;

        __syncthreads();
        if (lt < 28) shh[grp][lt] = xhres[base*28 + lt];
        if (lt < 8)  shs[grp][lt] = xstat[base*8 + lt];
        __syncthreads();

        float v;
        if (lt < 96) {
            v = x[base*96 + lt];
        } else {
            int j = lt - 96;
            float a = embed_b[j];
            #pragma unroll
            for (int k = 0; k < 28; k++) a = fmaf(shh[grp][k], embed_w[k*32 + j], a);
            v = tanhf(a);
        }
        float s1 = v, s2 = v*v;
        #pragma unroll
        for (int o = 16; o > 0; o >>= 1) {
            s1 += __shfl_xor_sync(0xffffffffu, s1, o);
            s2 += __shfl_xor_sync(0xffffffffu, s2, o);
        }
        if ((lt & 31) == 0) { r1[grp][lt>>5] = s1; r2[grp][lt>>5] = s2; }
        __syncthreads();
        s1 = r1[grp][0]+r1[grp][1]+r1[grp][2]+r1[grp][3];
        s2 = r2[grp][0]+r2[grp][1]+r2[grp][2]+r2[grp][3];
        float mu  = s1 * (1.0f/128.0f);
        float var = s2 * (1.0f/128.0f) - mu*mu;
        float rs  = rsqrtf(var + 1e-5f);
        float a = loan1_b[lt];
        #pragma unroll
        for (int k = 0; k < 8; k++) a = fmaf(shs[grp][k], loan1_w[k*128 + lt], a);
        S_xn[(size_t)tok*DIN + lt] = (v - mu)*rs + tanhf(a);
    }
}

// ================= K1: in_proj tf32-TC GEMM  u = xn @ W (128 x 266) =================
// BM=128, BN=64, K=128, 256 threads (8 warps: 4x2), grid (5 n-blocks, 1920 m-blocks)
__global__ void k1_inproj(const float* __restrict__ W)
{
    extern __shared__ unsigned smu[];
    unsigned* As = smu;               // [128][132]
    unsigned* Bs = smu + 128*132;     // [64][132]  transposed: Bs[n][k]
    const int tid = threadIdx.x;
    const int n_base = blockIdx.x * 64;
    const int m_base = blockIdx.y * 128;

    for (int i = tid; i < 128*32; i += 256) {
        int m = i >> 5, k4 = i & 31;
        float4 v = *(const float4*)(S_xn + (size_t)(m_base+m)*128 + k4*4);
        unsigned* dst = As + m*132 + k4*4;
        dst[0] = f2tf32(v.x); dst[1] = f2tf32(v.y);
        dst[2] = f2tf32(v.z); dst[3] = f2tf32(v.w);
    }
    for (int i = tid; i < 64*128; i += 256) {
        int n = i >> 7, k = i & 127;
        int gn = n_base + n;
        float v = (gn < DPROJ) ? W[(size_t)k*DPROJ + gn] : 0.0f;
        Bs[n*132 + k] = f2tf32(v);
    }
    __syncthreads();

    const int warp = tid >> 5, lane = tid & 31;
    const int gid = lane >> 2, tg = lane & 3;
    const int wm = warp & 3, wn = warp >> 2;

    float acc[2][4][4] = {};
    #pragma unroll 4
    for (int ks = 0; ks < 16; ks++) {
        const int k0 = ks*8;
        unsigned af[2][4], bf[4][2];
        #pragma unroll
        for (int mt = 0; mt < 2; mt++) {
            const unsigned* p = As + (wm*32 + mt*16 + gid)*132 + k0 + tg;
            af[mt][0] = p[0]; af[mt][1] = p[8*132];
            af[mt][2] = p[4]; af[mt][3] = p[8*132+4];
        }
        #pragma unroll
        for (int nt = 0; nt < 4; nt++) {
            const unsigned* p = Bs + (wn*32 + nt*8 + gid)*132 + k0 + tg;
            bf[nt][0] = p[0]; bf[nt][1] = p[4];
        }
        #pragma unroll
        for (int mt = 0; mt < 2; mt++)
            #pragma unroll
            for (int nt = 0; nt < 4; nt++)
                mma_tf32(acc[mt][nt], af[mt], bf[nt]);
    }

    #pragma unroll
    for (int mt = 0; mt < 2; mt++) {
        int row = m_base + wm*32 + mt*16 + gid;
        #pragma unroll
        for (int nt = 0; nt < 4; nt++) {
            int col = n_base + wn*32 + nt*8 + tg*2;
            if (col < DPROJ) {
                *(float2*)(S_u + (size_t)row*DPROJ + col) =
                    make_float2(acc[mt][nt][0], acc[mt][nt][1]);
                *(float2*)(S_u + (size_t)(row+8)*DPROJ + col) =
                    make_float2(acc[mt][nt][2], acc[mt][nt][3]);
            }
        }
    }
}

// ================= K2: mamba per-sequence (fwd+bwd) =================
__global__ void k2_mamba(
    const float* __restrict__ cw_f, const float* __restrict__ cb_f,
    const float* __restrict__ dtb_f, const float* __restrict__ al_f,
    const float* __restrict__ Dp_f, const float* __restrict__ nw_f,
    const float* __restrict__ cw_b, const float* __restrict__ cb_b,
    const float* __restrict__ dtb_b, const float* __restrict__ al_b,
    const float* __restrict__ Dp_b, const float* __restrict__ nw_b)
{
    extern __shared__ float sm2[];
    float* u_s  = sm2;                 // [30][268]
    float* xc_s = u_s + 30*268;        // [30][132]
    float* dt_s = xc_s + 30*132;       // [30][8]
    float* dA_s = dt_s + 240;          // [30][8]
    float* y_s  = dA_s + 240;          // [30][128]
    __shared__ float Aneg[8];

    const int blk = blockIdx.x;
    const int dir = blk >> 13;
    const int s   = blk & 8191;
    const int b   = s >> 12;
    const int sb  = s & 4095;
    const int tg  = sb >> 11;
    const int qg  = sb & 2047;
    const int tid = threadIdx.x;

    const float* conv_w = dir ? cw_b : cw_f;
    const float* conv_b = dir ? cb_b : cb_f;
    const float* dtb    = dir ? dtb_b : dtb_f;
    const float* alog   = dir ? al_b  : al_f;
    const float* Dp     = dir ? Dp_b  : Dp_f;
    const float* nw     = dir ? nw_b  : nw_f;
    float* ybuf         = dir ? S_yb  : S_yf;

    for (int l = 0; l < 30; l++) {
        int l10  = l / 10;
        int t_in = tg*3 + l10;
        int p0   = qg*10 + (l - l10*10);
        int p_in = dir ? (PP-1-p0) : p0;
        const float2* src = (const float2*)(S_u + ((size_t)(b*TT + t_in)*PP + p_in)*DPROJ);
        float2* dst = (float2*)(u_s + l*268);
        for (int i = tid; i < 133; i += 128) dst[i] = src[i];
    }
    if (tid < 8) Aneg[tid] = -expf(alog[tid]);
    __syncthreads();

    for (int i = tid; i < 240; i += 128) {
        int l = i >> 3, h = i & 7;
        float raw = u_s[l*268 + 258 + h] + dtb[h];
        float dt = (raw > 20.f) ? raw : log1pf(expf(raw));
        dt_s[l*8 + h] = dt;
        dA_s[l*8 + h] = expf(dt * Aneg[h]);
    }
    for (int c = tid; c < 130; c += 128) {
        float w0 = conv_w[c*3+0], w1 = conv_w[c*3+1], w2 = conv_w[c*3+2];
        float bias = conv_b[c];
        float p2 = 0.f, p1 = 0.f;
        #pragma unroll
        for (int l = 0; l < 30; l++) {
            float v = u_s[l*268 + 128 + c];
            float a = fmaf(p2, w0, fmaf(p1, w1, fmaf(v, w2, bias)));
            xc_s[l*132 + c] = a / (1.f + expf(-a));
            p2 = p1; p1 = v;
        }
    }
    __syncthreads();

    {
        const int c = tid, h = c >> 4;
        const float Dh = Dp[h];
        float hs = 0.f;
        #pragma unroll
        for (int l = 0; l < 30; l++) {
            float xv = xc_s[l*132 + c];
            float Bv = xc_s[l*132 + 128];
            float Cv = xc_s[l*132 + 129];
            hs = fmaf(hs, dA_s[l*8+h], dt_s[l*8+h]*xv*Bv);
            float y = fmaf(hs, Cv, xv*Dh);
            float z = u_s[l*268 + c];
            y *= z / (1.f + expf(-z));
            y_s[l*128 + c] = y;
        }
    }
    __syncthreads();

    const int warp = tid >> 5, lane = tid & 31;
    const int abase = (tg*1024 + (qg>>1))*6 + (qg&1);
    for (int l = warp; l < 30; l += 4) {
        float4 v = *(float4*)(y_s + l*128 + lane*4);
        float ss = v.x*v.x + v.y*v.y + v.z*v.z + v.w*v.w;
        #pragma unroll
        for (int o = 16; o > 0; o >>= 1) ss += __shfl_xor_sync(0xffffffffu, ss, o);
        float scale = rsqrtf(ss*(1.f/128.f) + 1e-5f) * 0.5f;
        int l3 = l / 3;
        int f = l3*12288 + abase + (l - l3*3)*2;
        int t_out = f / PP;
        int p_out = f - t_out*PP;
        if (dir) p_out = PP-1 - p_out;
        float4 w = *(const float4*)(nw + lane*4);
        float4 o;
        o.x = v.x*scale*w.x; o.y = v.y*scale*w.y;
        o.z = v.z*scale*w.z; o.w = v.w*scale*w.w;
        *(float4*)(ybuf + ((size_t)(b*TT + t_out)*PP + p_out)*128 + lane*4) = o;
    }
}

// ================= K3: x1 = xg + (yf+yb) @ out_proj ; LN + loan2 -> tt =================
// BM=64, N=96 (full), K=128, 256 threads (8 warps: 2x4), tf32 TC
__global__ void k3_outproj(const float* __restrict__ Wo,
                           const float* __restrict__ x,
                           const int*   __restrict__ curves,
                           const float* __restrict__ xstat,
                           const float* __restrict__ loan2_w,
                           const float* __restrict__ loan2_b)
{
    extern __shared__ unsigned smu3[];
    unsigned* As = smu3;               // [64][132]  (later overlaid by x1s [64][100])
    unsigned* Bs = smu3 + 64*132;      // [96][132]  transposed
    float* x1s = (float*)smu3;
    const int tid = threadIdx.x;
    const int m_base = blockIdx.x * 64;

    for (int i = tid; i < 64*32; i += 256) {
        int m = i >> 5, k4 = i & 31;
        size_t off = (size_t)(m_base+m)*128 + k4*4;
        float4 a  = *(const float4*)(S_yf + off);
        float4 bq = *(const float4*)(S_yb + off);
        unsigned* dst = As + m*132 + k4*4;
        dst[0] = f2tf32(a.x + bq.x); dst[1] = f2tf32(a.y + bq.y);
        dst[2] = f2tf32(a.z + bq.z); dst[3] = f2tf32(a.w + bq.w);
    }
    for (int i = tid; i < 96*128; i += 256) {
        int n = i >> 7, k = i & 127;
        Bs[n*132 + k] = f2tf32(Wo[(size_t)k*96 + n]);
    }
    __syncthreads();

    const int warp = tid >> 5, lane = tid & 31;
    const int gid = lane >> 2, tg = lane & 3;
    const int wm = warp & 1, wn = warp >> 1;   // wm: 2x32 rows, wn: 4x24 cols

    float acc[2][3][4] = {};
    #pragma unroll 4
    for (int ks = 0; ks < 16; ks++) {
        const int k0 = ks*8;
        unsigned af[2][4], bf[3][2];
        #pragma unroll
        for (int mt = 0; mt < 2; mt++) {
            const unsigned* p = As + (wm*32 + mt*16 + gid)*132 + k0 + tg;
            af[mt][0] = p[0]; af[mt][1] = p[8*132];
            af[mt][2] = p[4]; af[mt][3] = p[8*132+4];
        }
        #pragma unroll
        for (int nt = 0; nt < 3; nt++) {
            const unsigned* p = Bs + (wn*24 + nt*8 + gid)*132 + k0 + tg;
            bf[nt][0] = p[0]; bf[nt][1] = p[4];
        }
        #pragma unroll
        for (int mt = 0; mt < 2; mt++)
            #pragma unroll
            for (int nt = 0; nt < 3; nt++)
                mma_tf32(acc[mt][nt], af[mt], bf[nt]);
    }
    __syncthreads();  // done reading As -> overlay x1s

    #pragma unroll
    for (int mt = 0; mt < 2; mt++) {
        int r = wm*32 + mt*16 + gid;
        #pragma unroll
        for (int nt = 0; nt < 3; nt++) {
            int c = wn*24 + nt*8 + tg*2;
            x1s[r*100 + c]     = acc[mt][nt][0];
            x1s[r*100 + c + 1] = acc[mt][nt][1];
            x1s[(r+8)*100 + c]     = acc[mt][nt][2];
            x1s[(r+8)*100 + c + 1] = acc[mt][nt][3];
        }
    }
    __syncthreads();

    // per-row residual add + LN(96) + tanh(xs@loan2) -> S_x1, S_tt
    for (int r = warp; r < 64; r += 8) {
        int gm = m_base + r;
        int b  = gm / (TT*PP);
        int tp = gm - b*TT*PP;
        int t  = tp / PP;
        int p  = tp - t*PP;
        int g  = curves[b*PP + p];
        size_t xbase = ((size_t)(b*TT + t)*PP + g)*96;
        float v0 = x1s[r*100 + lane*3 + 0] + x[xbase + lane*3 + 0];
        float v1 = x1s[r*100 + lane*3 + 1] + x[xbase + lane*3 + 1];
        float v2 = x1s[r*100 + lane*3 + 2] + x[xbase + lane*3 + 2];
        S_x1[(size_t)gm*96 + lane*3 + 0] = v0;
        S_x1[(size_t)gm*96 + lane*3 + 1] = v1;
        S_x1[(size_t)gm*96 + lane*3 + 2] = v2;
        float s1 = v0+v1+v2, s2 = v0*v0+v1*v1+v2*v2;
        #pragma unroll
        for (int o = 16; o > 0; o >>= 1) {
            s1 += __shfl_xor_sync(0xffffffffu, s1, o);
            s2 += __shfl_xor_sync(0xffffffffu, s2, o);
        }
        float mu  = s1 * (1.0f/96.0f);
        float var = s2 * (1.0f/96.0f) - mu*mu;
        float rs  = rsqrtf(var + 1e-5f);
        size_t sbase = ((size_t)(b*TT + t)*PP + g)*8;
        float xs[8];
        #pragma unroll
        for (int k = 0; k < 8; k++) xs[k] = xstat[sbase + k];
        #pragma unroll
        for (int i2 = 0; i2 < 3; i2++) {
            int jj = lane*3 + i2;
            float a = loan2_b[jj];
            #pragma unroll
            for (int k = 0; k < 8; k++) a = fmaf(xs[k], loan2_w[k*96 + jj], a);
            float vv = (i2 == 0) ? v0 : ((i2 == 1) ? v1 : v2);
            S_tt[(size_t)gm*96 + jj] = (vv - mu)*rs + tanhf(a);
        }
    }
}

// ================= K4: generic 96x96 tf32-TC GEMM (two passes) =================
// BM=128, N=96, K=96, 256 threads (8 warps: 4x2)
// MODE 0: out = gelu(in@W + b)          (k4a: S_tt -> S_h)
// MODE 1: out = in@W + b + res          (k4b: S_h -> d_out)
template<int MODE>
__global__ void k4_gemm96(const float* __restrict__ in,
                          const float* __restrict__ Wg,
                          const float* __restrict__ bg,
                          const float* __restrict__ res,
                          float* __restrict__ out)
{
    extern __shared__ unsigned smu4[];
    unsigned* As = smu4;               // [128][100]
    unsigned* Bs = smu4 + 128*100;     // [96][100] transposed
    const int tid = threadIdx.x;
    const int m_base = blockIdx.x * 128;

    for (int i = tid; i < 128*24; i += 256) {
        int m = i / 24, c4 = i - (i/24)*24;
        float4 v = *(const float4*)(in + (size_t)(m_base+m)*96 + c4*4);
        unsigned* dst = As + m*100 + c4*4;
        dst[0] = f2tf32(v.x); dst[1] = f2tf32(v.y);
        dst[2] = f2tf32(v.z); dst[3] = f2tf32(v.w);
    }
    for (int i = tid; i < 96*96; i += 256) {
        int n = i / 96, k = i - (i/96)*96;
        Bs[n*100 + k] = f2tf32(Wg[(size_t)k*96 + n]);
    }
    __syncthreads();

    const int warp = tid >> 5, lane = tid & 31;
    const int gid = lane >> 2, tg = lane & 3;
    const int wm = warp & 3, wn = warp >> 2;   // wm: 4x32 rows, wn: 2x48 cols

    float acc[2][6][4] = {};
    #pragma unroll 3
    for (int ks = 0; ks < 12; ks++) {
        const int k0 = ks*8;
        unsigned af[2][4], bf[6][2];
        #pragma unroll
        for (int mt = 0; mt < 2; mt++) {
            const unsigned* p = As + (wm*32 + mt*16 + gid)*100 + k0 + tg;
            af[mt][0] = p[0]; af[mt][1] = p[8*100];
            af[mt][2] = p[4]; af[mt][3] = p[8*100+4];
        }
        #pragma unroll
        for (int nt = 0; nt < 6; nt++) {
            const unsigned* p = Bs + (wn*48 + nt*8 + gid)*100 + k0 + tg;
            bf[nt][0] = p[0]; bf[nt][1] = p[4];
        }
        #pragma unroll
        for (int mt = 0; mt < 2; mt++)
            #pragma unroll
            for (int nt = 0; nt < 6; nt++)
                mma_tf32(acc[mt][nt], af[mt], bf[nt]);
    }

    #pragma unroll
    for (int mt = 0; mt < 2; mt++) {
        int row = m_base + wm*32 + mt*16 + gid;
        #pragma unroll
        for (int nt = 0; nt < 6; nt++) {
            int col = wn*48 + nt*8 + tg*2;
            float b0 = bg[col], b1v = bg[col+1];
            float o00 = acc[mt][nt][0] + b0, o01 = acc[mt][nt][1] + b1v;
            float o10 = acc[mt][nt][2] + b0, o11 = acc[mt][nt][3] + b1v;
            if (MODE == 0) {
                o00 = geluf(o00); o01 = geluf(o01);
                o10 = geluf(o10); o11 = geluf(o11);
            } else {
                float2 r0 = *(const float2*)(res + (size_t)row*96 + col);
                float2 r1 = *(const float2*)(res + (size_t)(row+8)*96 + col);
                o00 += r0.x; o01 += r0.y;
                o10 += r1.x; o11 += r1.y;
            }
            *(float2*)(out + (size_t)row*96 + col)     = make_float2(o00, o01);
            *(float2*)(out + (size_t)(row+8)*96 + col) = make_float2(o10, o11);
        }
    }
}

// ================= launcher =================
extern "C" void kernel_launch(void* const* d_in, const int* in_sizes, int n_in,
                              void* d_out, int out_size)
{
    const float* x       = (const float*)d_in[0];
    const float* xstat   = (const float*)d_in[1];
    const float* xhres   = (const float*)d_in[2];
    const int*   curves  = (const int*)  d_in[3];
    const float* embed_w = (const float*)d_in[4];
    const float* embed_b = (const float*)d_in[5];
    const float* loan1_w = (const float*)d_in[6];
    const float* loan1_b = (const float*)d_in[7];
    const float* loan2_w = (const float*)d_in[8];
    const float* loan2_b = (const float*)d_in[9];
    const float* in_proj = (const float*)d_in[10];
    const float* cw_f  = (const float*)d_in[11];
    const float* cb_f  = (const float*)d_in[12];
    const float* dtb_f = (const float*)d_in[13];
    const float* al_f  = (const float*)d_in[14];
    const float* Dp_f  = (const float*)d_in[15];
    const float* nw_f  = (const float*)d_in[16];
    const float* cw_b  = (const float*)d_in[17];
    const float* cb_b  = (const float*)d_in[18];
    const float* dtb_b = (const float*)d_in[19];
    const float* al_b  = (const float*)d_in[20];
    const float* Dp_b  = (const float*)d_in[21];
    const float* nw_b  = (const float*)d_in[22];
    const float* Wo    = (const float*)d_in[23];
    const float* W1    = (const float*)d_in[24];
    const float* b1    = (const float*)d_in[25];
    const float* W2    = (const float*)d_in[26];
    const float* b2    = (const float*)d_in[27];
    float* out = (float*)d_out;

    const int smem1 = (128*132 + 64*132) * 4;                   // 101376
    const int smem2 = (30*268 + 30*132 + 240 + 240 + 30*128)*4; // 65280
    const int smem3 = (64*132 + 96*132) * 4;                    // 84480
    const int smem4 = (128*100 + 96*100) * 4;                   // 89600

    cudaFuncSetAttribute(k1_inproj, cudaFuncAttributeMaxDynamicSharedMemorySize, smem1);
    cudaFuncSetAttribute(k2_mamba,  cudaFuncAttributeMaxDynamicSharedMemorySize, smem2);
    cudaFuncSetAttribute(k3_outproj,cudaFuncAttributeMaxDynamicSharedMemorySize, smem3);
    cudaFuncSetAttribute(k4_gemm96<0>, cudaFuncAttributeMaxDynamicSharedMemorySize, smem4);
    cudaFuncSetAttribute(k4_gemm96<1>, cudaFuncAttributeMaxDynamicSharedMemorySize, smem4);

    k0_prologue<<<NTOK/8, 512>>>(x, xstat, xhres, curves, embed_w, embed_b, loan1_w, loan1_b);

    // n-blocks fastest so the 5 N-tiles of one M-tile are launch-adjacent (L2 reuse of A)
    dim3 g1(5, NTOK/128);
    k1_inproj<<<g1, 256, smem1>>>(in_proj);

    k2_mamba<<<16384, 128, smem2>>>(cw_f, cb_f, dtb_f, al_f, Dp_f, nw_f,
                                    cw_b, cb_b, dtb_b, al_b, Dp_b, nw_b);

    k3_outproj<<<NTOK/64, 256, smem3>>>(Wo, x, curves, xstat, loan2_w, loan2_b);

    float* S_h = (float*)S_u;  // device-symbol address is identical in device code;
    (void)S_h;                 // kernels reference S_u directly via template arg below

    // k4a: S_h(=S_u scratch) = gelu(S_tt @ W1 + b1)
    {
        // get device pointer to S_u for use as in/out runtime args
        // (S_u is a __device__ symbol; take its address inside a tiny launch-safe way:
        //  we simply pass it via kernels that reference the symbol directly is not
        //  possible for a generic kernel, so use cudaGetSymbolAddress once per call —
        //  host API, no allocation, graph-capture safe.)
        static float* s_u_ptr = nullptr;
        static float* s_tt_ptr = nullptr;
        static float* s_x1_ptr = nullptr;
        if (!s_u_ptr) {
            cudaGetSymbolAddress((void**)&s_u_ptr, S_u);
            cudaGetSymbolAddress((void**)&s_tt_ptr, S_tt);
            cudaGetSymbolAddress((void**)&s_x1_ptr, S_x1);
        }
        k4_gemm96<0><<<NTOK/128, 256, smem4>>>(s_tt_ptr, W1, b1, nullptr, s_u_ptr);
        k4_gemm96<1><<<NTOK/128, 256, smem4>>>(s_u_ptr, W2, b2, s_x1_ptr, out);
    }
}

// round 3
// speedup vs baseline: 1.3485x; 1.3382x over previous
#include <cuda_runtime.h>
#include <math.h>

#define BB 2
#define TT 6
#define PP 20480
#define NTOK (BB*TT*PP)      /* 245760 */
#define DPROJ 266

// ---------------- scratch ----------------
__device__ float S_xn[(size_t)NTOK*128];
__device__ float S_u [(size_t)NTOK*DPROJ];
__device__ float S_yf[(size_t)NTOK*128];
__device__ float S_yb[(size_t)NTOK*128];

__device__ __forceinline__ float geluf(float v) {
    return 0.5f * v * (1.0f + erff(v * 0.70710678118654752f));
}
__device__ __forceinline__ unsigned f2tf32(float f) {
    unsigned r;
    asm("cvt.rna.tf32.f32 %0, %1;" : "=r"(r) : "f"(f));
    return r;
}
// permute k within 16-groups: orig j -> 4*(j%4) + j/4  (4x4 transpose)
__device__ __forceinline__ int kperm16(int k) {
    int g = k & ~15, j = k & 15;
    return g + ((j & 3) << 2) + (j >> 2);
}
__device__ __forceinline__ void mma_tf32(float* c, const unsigned* a, const unsigned* b) {
    asm volatile(
        "mma.sync.aligned.m16n8k8.row.col.f32.tf32.tf32.f32 "
        "{%0,%1,%2,%3}, {%4,%5,%6,%7}, {%8,%9}, {%0,%1,%2,%3};"
        : "+f"(c[0]), "+f"(c[1]), "+f"(c[2]), "+f"(c[3])
        : "r"(a[0]), "r"(a[1]), "r"(a[2]), "r"(a[3]), "r"(b[0]), "r"(b[1]));
}
// scatter-store 4 converted floats of an orig-k float4 (word idx c, i.e. k=4c..4c+3)
__device__ __forceinline__ void stage4(unsigned* row, int sw, int c, float x, float y, float z, float w) {
    int g = (c >> 2) << 4, r = c & 3;
    row[(g + r     ) ^ sw] = f2tf32(x);
    row[(g + r + 4 ) ^ sw] = f2tf32(y);
    row[(g + r + 8 ) ^ sw] = f2tf32(z);
    row[(g + r + 12) ^ sw] = f2tf32(w);
}

// ================= K0: gather + embed + LN + loan1 -> xn =================
__global__ void k0_prologue(const float* __restrict__ x,
                            const float* __restrict__ xstat,
                            const float* __restrict__ xhres,
                            const int*   __restrict__ curves,
                            const float* __restrict__ embed_w,
                            const float* __restrict__ embed_b,
                            const float* __restrict__ loan1_w,
                            const float* __restrict__ loan1_b)
{
    const int tid = threadIdx.x;
    const int grp = tid >> 7;
    const int lt  = tid & 127;
    __shared__ float shh[4][28];
    __shared__ float shs[4][8];
    __shared__ float r1[4][4], r2[4][4];

    for (int it = 0; it < 2; it++) {
        const int tok = blockIdx.x * 8 + it * 4 + grp;
        const int b  = tok / (TT*PP);
        const int tp = tok - b*TT*PP;
        const int t  = tp / PP;
        const int p  = tp - t*PP;
        const int g  = curves[b*PP + p];
        const size_t base = (size_t)(b*TT + t)*PP + g;

        __syncthreads();
        if (lt < 28) shh[grp][lt] = xhres[base*28 + lt];
        if (lt < 8)  shs[grp][lt] = xstat[base*8 + lt];
        __syncthreads();

        float v;
        if (lt < 96) {
            v = x[base*96 + lt];
        } else {
            int j = lt - 96;
            float a = embed_b[j];
            #pragma unroll
            for (int k = 0; k < 28; k++) a = fmaf(shh[grp][k], embed_w[k*32 + j], a);
            v = tanhf(a);
        }
        float s1 = v, s2 = v*v;
        #pragma unroll
        for (int o = 16; o > 0; o >>= 1) {
            s1 += __shfl_xor_sync(0xffffffffu, s1, o);
            s2 += __shfl_xor_sync(0xffffffffu, s2, o);
        }
        if ((lt & 31) == 0) { r1[grp][lt>>5] = s1; r2[grp][lt>>5] = s2; }
        __syncthreads();
        s1 = r1[grp][0]+r1[grp][1]+r1[grp][2]+r1[grp][3];
        s2 = r2[grp][0]+r2[grp][1]+r2[grp][2]+r2[grp][3];
        float mu  = s1 * (1.0f/128.0f);
        float var = s2 * (1.0f/128.0f) - mu*mu;
        float rs  = rsqrtf(var + 1e-5f);
        float a = loan1_b[lt];
        #pragma unroll
        for (int k = 0; k < 8; k++) a = fmaf(shs[grp][k], loan1_w[k*128 + lt], a);
        S_xn[(size_t)tok*128 + lt] = (v - mu)*rs + tanhf(a);
    }
}

// ================= K1: in_proj tf32 TC GEMM (perm+swizzle frags) =================
// BM=128, BN=64, K=128, 256 threads (8 warps: 4m x 2n)
__global__ void k1_inproj(const float* __restrict__ W)
{
    extern __shared__ unsigned smu[];
    unsigned* As = smu;               // [128][128] swizzled
    unsigned* Bs = smu + 128*128;     // [64][128]  swizzled (B^T)
    const int tid = threadIdx.x;
    const int n_base = blockIdx.x * 64;
    const int m_base = blockIdx.y * 128;

    for (int i = tid; i < 128*32; i += 256) {
        int m = i >> 5, c = i & 31;
        float4 v = *(const float4*)(S_xn + (size_t)(m_base+m)*128 + c*4);
        stage4(As + m*128, (m&1)<<4, c, v.x, v.y, v.z, v.w);
    }
    for (int i = tid; i < 64*128; i += 256) {
        int n = i >> 7, k = i & 127;
        int gn = n_base + n;
        float v = (gn < DPROJ) ? W[(size_t)k*DPROJ + gn] : 0.0f;
        Bs[n*128 + (kperm16(k) ^ ((n&1)<<4))] = f2tf32(v);
    }
    __syncthreads();

    const int warp = tid >> 5, lane = tid & 31;
    const int gid = lane >> 2, tg = lane & 3;
    const int wm = warp & 3, wn = warp >> 2;

    float acc[2][4][4] = {};
    #pragma unroll
    for (int it = 0; it < 8; it++) {
        const int cb = it*16 + tg*4;
        uint4 a0[2], a8[2], bv[4];
        #pragma unroll
        for (int mt = 0; mt < 2; mt++) {
            int r0 = wm*32 + mt*16 + gid;
            int sw = (r0 & 1) << 4;
            a0[mt] = *(const uint4*)(As + r0*128 + (cb ^ sw));
            a8[mt] = *(const uint4*)(As + (r0+8)*128 + (cb ^ sw));
        }
        #pragma unroll
        for (int nt = 0; nt < 4; nt++) {
            int nr = wn*32 + nt*8 + gid;
            int sw = (nr & 1) << 4;
            bv[nt] = *(const uint4*)(Bs + nr*128 + (cb ^ sw));
        }
        #pragma unroll
        for (int mt = 0; mt < 2; mt++) {
            #pragma unroll
            for (int nt = 0; nt < 4; nt++) {
                unsigned a1[4] = {a0[mt].x, a8[mt].x, a0[mt].y, a8[mt].y};
                unsigned b1v[2] = {bv[nt].x, bv[nt].y};
                mma_tf32(acc[mt][nt], a1, b1v);
                unsigned a2[4] = {a0[mt].z, a8[mt].z, a0[mt].w, a8[mt].w};
                unsigned b2v[2] = {bv[nt].z, bv[nt].w};
                mma_tf32(acc[mt][nt], a2, b2v);
            }
        }
    }

    #pragma unroll
    for (int mt = 0; mt < 2; mt++) {
        int row = m_base + wm*32 + mt*16 + gid;
        #pragma unroll
        for (int nt = 0; nt < 4; nt++) {
            int col = n_base + wn*32 + nt*8 + tg*2;
            if (col < DPROJ) {
                *(float2*)(S_u + (size_t)row*DPROJ + col) =
                    make_float2(acc[mt][nt][0], acc[mt][nt][1]);
                *(float2*)(S_u + (size_t)(row+8)*DPROJ + col) =
                    make_float2(acc[mt][nt][2], acc[mt][nt][3]);
            }
        }
    }
}

// ================= K2: mamba, fwd+bwd fused per u-tile =================
// 8192 blocks, 256 threads (tid>>7 = direction); bwd(tg,2047-qg) shares fwd(tg,qg)'s rows
__global__ void k2_mamba(
    const float* __restrict__ cw_f, const float* __restrict__ cb_f,
    const float* __restrict__ dtb_f, const float* __restrict__ al_f,
    const float* __restrict__ Dp_f, const float* __restrict__ nw_f,
    const float* __restrict__ cw_b, const float* __restrict__ cb_b,
    const float* __restrict__ dtb_b, const float* __restrict__ al_b,
    const float* __restrict__ Dp_b, const float* __restrict__ nw_b)
{
    extern __shared__ float sm2[];
    float* u_s = sm2;                    // [30][268]
    float* xc0 = u_s + 30*268;           // [30][132]
    float* xc1 = xc0 + 30*132;
    float* dt0 = xc1 + 30*132;           // [30][8]
    float* dA0 = dt0 + 240;
    float* dt1 = dA0 + 240;
    float* dA1 = dt1 + 240;
    float* y0  = dA1 + 240;              // [30][128]
    float* y1  = y0 + 30*128;
    __shared__ float Aneg[2][8];

    const int s   = blockIdx.x;
    const int b   = s >> 12;
    const int tg  = (s >> 11) & 1;
    const int qg  = s & 2047;
    const int tid = threadIdx.x;
    const int dir = tid >> 7;
    const int lt  = tid & 127;

    // flat, MLP-rich load of the 30 shared rows
    for (int i = tid; i < 30*133; i += 256) {
        int l  = i / 133;
        int cc = i - l*133;
        int t_in = tg*3 + l/10;
        int p0   = qg*10 + (l - (l/10)*10);
        *(float2*)(u_s + l*268 + cc*2) =
            *(const float2*)(S_u + ((size_t)(b*TT + t_in)*PP + p0)*DPROJ + cc*2);
    }
    if (tid < 16) Aneg[tid>>3][tid&7] = -expf((tid < 8 ? al_f : al_b)[tid & 7]);
    __syncthreads();

    const float* conv_w = dir ? cw_b  : cw_f;
    const float* conv_b = dir ? cb_b  : cb_f;
    const float* dtbp   = dir ? dtb_b : dtb_f;
    const float* Dpp    = dir ? Dp_b  : Dp_f;
    float* xc  = dir ? xc1 : xc0;
    float* dts = dir ? dt1 : dt0;
    float* dAs = dir ? dA1 : dA0;
    float* ys  = dir ? y1  : y0;

    // dt/dA (bwd step l maps to fwd-loaded row lu)
    for (int i = lt; i < 240; i += 128) {
        int l = i >> 3, h = i & 7;
        int lu = dir ? ((l/10)*10 + 9 - (l - (l/10)*10)) : l;
        float raw = u_s[lu*268 + 258 + h] + dtbp[h];
        float dt = (raw > 20.f) ? raw : log1pf(expf(raw));
        dts[l*8 + h] = dt;
        dAs[l*8 + h] = expf(dt * Aneg[dir][h]);
    }
    // causal depthwise conv + silu
    for (int c = lt; c < 130; c += 128) {
        float w0 = conv_w[c*3+0], w1 = conv_w[c*3+1], w2 = conv_w[c*3+2];
        float bias = conv_b[c];
        float p2 = 0.f, p1 = 0.f;
        #pragma unroll
        for (int l = 0; l < 30; l++) {
            int lu = dir ? ((l/10)*10 + 9 - (l - (l/10)*10)) : l;
            float v = u_s[lu*268 + 128 + c];
            float a = fmaf(p2, w0, fmaf(p1, w1, fmaf(v, w2, bias)));
            xc[l*132 + c] = a / (1.f + expf(-a));
            p2 = p1; p1 = v;
        }
    }
    __syncthreads();

    // scalar scan (D_STATE=1), thread = channel
    {
        const int c = lt, h = c >> 4;
        const float Dh = Dpp[h];
        float hs = 0.f;
        #pragma unroll
        for (int l = 0; l < 30; l++) {
            int lu = dir ? ((l/10)*10 + 9 - (l - (l/10)*10)) : l;
            float xv = xc[l*132 + c];
            float Bv = xc[l*132 + 128];
            float Cv = xc[l*132 + 129];
            hs = fmaf(hs, dAs[l*8+h], dts[l*8+h]*xv*Bv);
            float y = fmaf(hs, Cv, xv*Dh);
            float z = u_s[lu*268 + c];
            y *= z / (1.f + expf(-z));
            ys[l*128 + c] = y;
        }
    }
    __syncthreads();

    // RMS + scatter to _wrev positions
    const int warp = tid >> 5, lane = tid & 31;
    const int dw = warp >> 2, w4 = warp & 3;
    const float* nww = dw ? nw_b : nw_f;
    float* yss  = dw ? y1 : y0;
    float* ybuf = dw ? S_yb : S_yf;
    const int qgu = dw ? (2047 - qg) : qg;
    const int abase = (tg*1024 + (qgu>>1))*6 + (qgu&1);
    for (int l = w4; l < 30; l += 4) {
        float4 v = *(float4*)(yss + l*128 + lane*4);
        float ss = v.x*v.x + v.y*v.y + v.z*v.z + v.w*v.w;
        #pragma unroll
        for (int o = 16; o > 0; o >>= 1) ss += __shfl_xor_sync(0xffffffffu, ss, o);
        float scale = rsqrtf(ss*(1.f/128.f) + 1e-5f) * 0.5f;
        int l3 = l / 3;
        int f = l3*12288 + abase + (l - l3*3)*2;
        int t_out = f / PP;
        int p_out = f - t_out*PP;
        if (dw) p_out = PP-1 - p_out;
        float4 w = *(const float4*)(nww + lane*4);
        float4 o;
        o.x = v.x*scale*w.x; o.y = v.y*scale*w.y;
        o.z = v.z*scale*w.z; o.w = v.w*scale*w.w;
        *(float4*)(ybuf + ((size_t)(b*TT + t_out)*PP + p_out)*128 + lane*4) = o;
    }
}

// ===== GEMM chunk for k34: M64xN96 over a k-chunk staged in Wb[96][48] =====
template<int NIT>
__device__ __forceinline__ void gemm_chunk(const unsigned* __restrict__ Ab, int SA,
                                           const unsigned* __restrict__ Wb,
                                           int ckbase, int wm, int wn, int gid, int tg,
                                           float (&acc)[2][3][4])
{
    #pragma unroll
    for (int it = 0; it < NIT; it++) {
        const int cbA = ckbase + it*16 + tg*4;
        const int cbB = it*16 + tg*4;
        uint4 a0[2], a8[2], bv[3];
        #pragma unroll
        for (int mt = 0; mt < 2; mt++) {
            int r0 = wm*32 + mt*16 + gid;
            int sw = (r0 & 1) << 4;
            a0[mt] = *(const uint4*)(Ab + r0*SA + (cbA ^ sw));
            a8[mt] = *(const uint4*)(Ab + (r0+8)*SA + (cbA ^ sw));
        }
        #pragma unroll
        for (int nt = 0; nt < 3; nt++) {
            int nr = wn*24 + nt*8 + gid;
            bv[nt] = *(const uint4*)(Wb + nr*48 + cbB);
        }
        #pragma unroll
        for (int mt = 0; mt < 2; mt++) {
            #pragma unroll
            for (int nt = 0; nt < 3; nt++) {
                unsigned a1[4] = {a0[mt].x, a8[mt].x, a0[mt].y, a8[mt].y};
                unsigned b1v[2] = {bv[nt].x, bv[nt].y};
                mma_tf32(acc[mt][nt], a1, b1v);
                unsigned a2[4] = {a0[mt].z, a8[mt].z, a0[mt].w, a8[mt].w};
                unsigned b2v[2] = {bv[nt].z, bv[nt].w};
                mma_tf32(acc[mt][nt], a2, b2v);
            }
        }
    }
}

__device__ __forceinline__ void fillW(unsigned* Wb, const float* __restrict__ Wsrc,
                                      int k0, int w, int tid)
{
    for (int i = tid; i < 96*w; i += 256) {
        int n = i / w, kk = i - n*w;
        Wb[n*48 + kperm16(kk)] = f2tf32(Wsrc[(size_t)(k0+kk)*96 + n]);
    }
}

// ================= K34: out_proj + residual + LN + loan2 + MLP, fully fused =================
// BM=64, 256 threads (8 warps: 2m x 4n), 2 CTAs/SM
__global__ void k34_fused(const float* __restrict__ Wo,
                          const float* __restrict__ x,
                          const int*   __restrict__ curves,
                          const float* __restrict__ xstat,
                          const float* __restrict__ loan2_w,
                          const float* __restrict__ loan2_b,
                          const float* __restrict__ W1,
                          const float* __restrict__ b1,
                          const float* __restrict__ W2,
                          const float* __restrict__ b2,
                          float* __restrict__ out)
{
    extern __shared__ unsigned smf[];
    unsigned* As  = smf;                       // [64][128] (GEMM0 A); later hs [64][96]
    unsigned* Wb  = smf + 64*128;              // [96][48]
    float*    x1s = (float*)(smf + 64*128 + 96*48);  // [64][100]
    unsigned* tts = smf + 64*128 + 96*48 + 64*100;   // [64][96]
    unsigned* hs  = As;

    const int tid = threadIdx.x;
    const int m_base = blockIdx.x * 64;
    const int warp = tid >> 5, lane = tid & 31;
    const int gid = lane >> 2, tg = lane & 3;
    const int wm = warp & 1, wn = warp >> 1;

    // stage A = yf + yb (tf32, perm+swizzle)
    for (int i = tid; i < 64*32; i += 256) {
        int m = i >> 5, c = i & 31;
        size_t off = (size_t)(m_base+m)*128 + c*4;
        float4 a = *(const float4*)(S_yf + off);
        float4 q = *(const float4*)(S_yb + off);
        stage4(As + m*128, (m&1)<<4, c, a.x+q.x, a.y+q.y, a.z+q.z, a.w+q.w);
    }
    fillW(Wb, Wo, 0, 48, tid);
    __syncthreads();

    // ---- GEMM0: (yf+yb) @ Wo  (K=128, chunks 48/48/32) ----
    float acc[2][3][4] = {};
    gemm_chunk<3>(As, 128, Wb, 0, wm, wn, gid, tg, acc);
    __syncthreads();
    fillW(Wb, Wo, 48, 48, tid);
    __syncthreads();
    gemm_chunk<3>(As, 128, Wb, 48, wm, wn, gid, tg, acc);
    __syncthreads();
    fillW(Wb, Wo, 96, 32, tid);
    __syncthreads();
    gemm_chunk<2>(As, 128, Wb, 96, wm, wn, gid, tg, acc);

    // store raw acc -> x1s
    #pragma unroll
    for (int mt = 0; mt < 2; mt++) {
        int r = wm*32 + mt*16 + gid;
        #pragma unroll
        for (int nt = 0; nt < 3; nt++) {
            int c = wn*24 + nt*8 + tg*2;
            x1s[r*100 + c]     = acc[mt][nt][0];
            x1s[r*100 + c + 1] = acc[mt][nt][1];
            x1s[(r+8)*100 + c]     = acc[mt][nt][2];
            x1s[(r+8)*100 + c + 1] = acc[mt][nt][3];
        }
    }
    __syncthreads();

    // ---- residual + LN + loan2 -> tts (tf32 perm+swizzle); x1 kept in x1s ----
    for (int r = warp; r < 64; r += 8) {
        int gm = m_base + r;
        int b  = gm / (TT*PP);
        int tp = gm - b*TT*PP;
        int t  = tp / PP;
        int p  = tp - t*PP;
        int g  = curves[b*PP + p];
        size_t xb = ((size_t)(b*TT + t)*PP + g)*96;
        float v0 = x1s[r*100 + lane*3 + 0] + x[xb + lane*3 + 0];
        float v1 = x1s[r*100 + lane*3 + 1] + x[xb + lane*3 + 1];
        float v2 = x1s[r*100 + lane*3 + 2] + x[xb + lane*3 + 2];
        x1s[r*100 + lane*3 + 0] = v0;
        x1s[r*100 + lane*3 + 1] = v1;
        x1s[r*100 + lane*3 + 2] = v2;
        float s1 = v0+v1+v2, s2 = v0*v0+v1*v1+v2*v2;
        #pragma unroll
        for (int o = 16; o > 0; o >>= 1) {
            s1 += __shfl_xor_sync(0xffffffffu, s1, o);
            s2 += __shfl_xor_sync(0xffffffffu, s2, o);
        }
        float mu  = s1 * (1.0f/96.0f);
        float var = s2 * (1.0f/96.0f) - mu*mu;
        float rs  = rsqrtf(var + 1e-5f);
        size_t sbase = ((size_t)(b*TT + t)*PP + g)*8;
        float xs[8];
        #pragma unroll
        for (int k = 0; k < 8; k++) xs[k] = xstat[sbase + k];
        int swr = (r & 1) << 4;
        #pragma unroll
        for (int i2 = 0; i2 < 3; i2++) {
            int jj = lane*3 + i2;
            float a = loan2_b[jj];
            #pragma unroll
            for (int k = 0; k < 8; k++) a = fmaf(xs[k], loan2_w[k*96 + jj], a);
            float vv = (i2 == 0) ? v0 : ((i2 == 1) ? v1 : v2);
            tts[r*96 + (kperm16(jj) ^ swr)] = f2tf32((vv - mu)*rs + tanhf(a));
        }
    }
    __syncthreads();

    // ---- GEMM1: tt @ W1 (K=96, chunks 48/48) ----
    float acc1[2][3][4] = {};
    fillW(Wb, W1, 0, 48, tid);
    __syncthreads();
    gemm_chunk<3>(tts, 96, Wb, 0, wm, wn, gid, tg, acc1);
    __syncthreads();
    fillW(Wb, W1, 48, 48, tid);
    __syncthreads();
    gemm_chunk<3>(tts, 96, Wb, 48, wm, wn, gid, tg, acc1);

    // gelu -> hs (overlays As; As dead)
    #pragma unroll
    for (int mt = 0; mt < 2; mt++) {
        int r = wm*32 + mt*16 + gid;
        int swr = (r & 1) << 4;
        #pragma unroll
        for (int nt = 0; nt < 3; nt++) {
            int c = wn*24 + nt*8 + tg*2;
            float bb0 = b1[c], bb1 = b1[c+1];
            hs[r*96 + (kperm16(c)   ^ swr)] = f2tf32(geluf(acc1[mt][nt][0] + bb0));
            hs[r*96 + (kperm16(c+1) ^ swr)] = f2tf32(geluf(acc1[mt][nt][1] + bb1));
            hs[(r+8)*96 + (kperm16(c)   ^ swr)] = f2tf32(geluf(acc1[mt][nt][2] + bb0));
            hs[(r+8)*96 + (kperm16(c+1) ^ swr)] = f2tf32(geluf(acc1[mt][nt][3] + bb1));
        }
    }
    __syncthreads();

    // ---- GEMM2: h @ W2 (K=96, chunks 48/48) ----
    float acc2[2][3][4] = {};
    fillW(Wb, W2, 0, 48, tid);
    __syncthreads();
    gemm_chunk<3>(hs, 96, Wb, 0, wm, wn, gid, tg, acc2);
    __syncthreads();
    fillW(Wb, W2, 48, 48, tid);
    __syncthreads();
    gemm_chunk<3>(hs, 96, Wb, 48, wm, wn, gid, tg, acc2);

    // final: out = x1 + acc2 + b2
    #pragma unroll
    for (int mt = 0; mt < 2; mt++) {
        int r = wm*32 + mt*16 + gid;
        int gm0 = m_base + r, gm8 = gm0 + 8;
        #pragma unroll
        for (int nt = 0; nt < 3; nt++) {
            int c = wn*24 + nt*8 + tg*2;
            float bb0 = b2[c], bb1 = b2[c+1];
            *(float2*)(out + (size_t)gm0*96 + c) = make_float2(
                acc2[mt][nt][0] + bb0 + x1s[r*100 + c],
                acc2[mt][nt][1] + bb1 + x1s[r*100 + c + 1]);
            *(float2*)(out + (size_t)gm8*96 + c) = make_float2(
                acc2[mt][nt][2] + bb0 + x1s[(r+8)*100 + c],
                acc2[mt][nt][3] + bb1 + x1s[(r+8)*100 + c + 1]);
        }
    }
}

// ================= launcher =================
extern "C" void kernel_launch(void* const* d_in, const int* in_sizes, int n_in,
                              void* d_out, int out_size)
{
    const float* x       = (const float*)d_in[0];
    const float* xstat   = (const float*)d_in[1];
    const float* xhres   = (const float*)d_in[2];
    const int*   curves  = (const int*)  d_in[3];
    const float* embed_w = (const float*)d_in[4];
    const float* embed_b = (const float*)d_in[5];
    const float* loan1_w = (const float*)d_in[6];
    const float* loan1_b = (const float*)d_in[7];
    const float* loan2_w = (const float*)d_in[8];
    const float* loan2_b = (const float*)d_in[9];
    const float* in_proj = (const float*)d_in[10];
    const float* cw_f  = (const float*)d_in[11];
    const float* cb_f  = (const float*)d_in[12];
    const float* dtb_f = (const float*)d_in[13];
    const float* al_f  = (const float*)d_in[14];
    const float* Dp_f  = (const float*)d_in[15];
    const float* nw_f  = (const float*)d_in[16];
    const float* cw_b  = (const float*)d_in[17];
    const float* cb_b  = (const float*)d_in[18];
    const float* dtb_b = (const float*)d_in[19];
    const float* al_b  = (const float*)d_in[20];
    const float* Dp_b  = (const float*)d_in[21];
    const float* nw_b  = (const float*)d_in[22];
    const float* Wo    = (const float*)d_in[23];
    const float* W1    = (const float*)d_in[24];
    const float* b1    = (const float*)d_in[25];
    const float* W2    = (const float*)d_in[26];
    const float* b2    = (const float*)d_in[27];
    float* out = (float*)d_out;

    const int smem1 = (128*128 + 64*128) * 4;                       // 98304
    const int smem2 = (30*268 + 2*30*132 + 4*240 + 2*30*128) * 4;   // 98400
    const int smem3 = (64*128 + 96*48 + 64*100 + 64*96) * 4;        // 101376

    cudaFuncSetAttribute(k1_inproj, cudaFuncAttributeMaxDynamicSharedMemorySize, smem1);
    cudaFuncSetAttribute(k2_mamba,  cudaFuncAttributeMaxDynamicSharedMemorySize, smem2);
    cudaFuncSetAttribute(k34_fused, cudaFuncAttributeMaxDynamicSharedMemorySize, smem3);

    k0_prologue<<<NTOK/8, 512>>>(x, xstat, xhres, curves, embed_w, embed_b, loan1_w, loan1_b);

    dim3 g1(5, NTOK/128);
    k1_inproj<<<g1, 256, smem1>>>(in_proj);

    k2_mamba<<<8192, 256, smem2>>>(cw_f, cb_f, dtb_f, al_f, Dp_f, nw_f,
                                   cw_b, cb_b, dtb_b, al_b, Dp_b, nw_b);

    k34_fused<<<NTOK/64, 256, smem3>>>(Wo, x, curves, xstat, loan2_w, loan2_b,
                                       W1, b1, W2, b2, out);
}

// round 4
// speedup vs baseline: 2.1409x; 1.5876x over previous
#include <cuda_runtime.h>
#include <math.h>

#define BB 2
#define TT 6
#define PP 20480
#define NTOK (BB*TT*PP)      /* 245760 */
#define DPROJ 266

// ---------------- scratch ----------------
__device__ float S_u [(size_t)NTOK*DPROJ];
__device__ float S_yf[(size_t)NTOK*128];
__device__ float S_yb[(size_t)NTOK*128];
// pre-permuted tf32 weights (B operands, n-major, kperm16'd)
__device__ unsigned Wp1[320*128];   // in_proj (n padded 266->320)
__device__ unsigned WoP[96*128];
__device__ unsigned W1P[96*96];
__device__ unsigned W2P[96*96];

__device__ __forceinline__ float geluf(float v) {
    return 0.5f * v * (1.0f + erff(v * 0.70710678118654752f));
}
__device__ __forceinline__ unsigned f2tf32(float f) {
    unsigned r;
    asm("cvt.rna.tf32.f32 %0, %1;" : "=r"(r) : "f"(f));
    return r;
}
__device__ __forceinline__ int kperm16(int k) {
    int g = k & ~15, j = k & 15;
    return g + ((j & 3) << 2) + (j >> 2);
}
__device__ __forceinline__ void mma_tf32(float* c, const unsigned* a, const unsigned* b) {
    asm volatile(
        "mma.sync.aligned.m16n8k8.row.col.f32.tf32.tf32.f32 "
        "{%0,%1,%2,%3}, {%4,%5,%6,%7}, {%8,%9}, {%0,%1,%2,%3};"
        : "+f"(c[0]), "+f"(c[1]), "+f"(c[2]), "+f"(c[3])
        : "r"(a[0]), "r"(a[1]), "r"(a[2]), "r"(a[3]), "r"(b[0]), "r"(b[1]));
}
__device__ __forceinline__ void stage4(unsigned* row, int sw, int c, float x, float y, float z, float w) {
    int g = (c >> 2) << 4, r = c & 3;
    row[(g + r     ) ^ sw] = f2tf32(x);
    row[(g + r + 4 ) ^ sw] = f2tf32(y);
    row[(g + r + 8 ) ^ sw] = f2tf32(z);
    row[(g + r + 12) ^ sw] = f2tf32(w);
}

// ================= prep: convert/permute weights once =================
__global__ void kprep(const float* __restrict__ inproj, const float* __restrict__ Wo,
                      const float* __restrict__ W1, const float* __restrict__ W2)
{
    int i = blockIdx.x * 256 + threadIdx.x;
    if (i < 320*128) {
        int n = i >> 7, k = i & 127;
        float v = (n < DPROJ) ? inproj[(size_t)k*DPROJ + n] : 0.0f;
        Wp1[n*128 + kperm16(k)] = f2tf32(v);
    }
    if (i < 96*128) {
        int n = i >> 7, k = i & 127;
        WoP[n*128 + kperm16(k)] = f2tf32(Wo[(size_t)k*96 + n]);
    }
    if (i < 96*96) {
        int n = i / 96, k = i - n*96;
        W1P[n*96 + kperm16(k)] = f2tf32(W1[(size_t)k*96 + n]);
        W2P[n*96 + kperm16(k)] = f2tf32(W2[(size_t)k*96 + n]);
    }
}

// ================= K01: fused prologue + in_proj GEMM =================
// BM=128, 256 threads (8 warps), 5 sequential n-tiles of 64, B frags via LDG
__global__ void __launch_bounds__(256, 3) k01_inproj(
    const float* __restrict__ x,
    const float* __restrict__ xstat,
    const float* __restrict__ xhres,
    const int*   __restrict__ curves,
    const float* __restrict__ embed_w,
    const float* __restrict__ embed_b,
    const float* __restrict__ loan1_w,
    const float* __restrict__ loan1_b)
{
    extern __shared__ unsigned As[];   // [128][128] swizzled tf32
    const int tid = threadIdx.x;
    const int warp = tid >> 5, lane = tid & 31;
    const int m_base = blockIdx.x * 128;

    // ---- prologue: warp-per-token, 16 passes ----
    for (int pass = 0; pass < 16; pass++) {
        const int m = pass*8 + warp;
        const int tok = m_base + m;
        const int b  = tok / (TT*PP);
        const int tp = tok - b*TT*PP;
        const int t  = tp / PP;
        const int p  = tp - t*PP;
        const int g  = curves[b*PP + p];
        const size_t base = (size_t)(b*TT + t)*PP + g;

        float hval = (lane < 28) ? xhres[base*28 + lane] : 0.0f;
        float sval = (lane < 8)  ? xstat[base*8 + lane]  : 0.0f;

        // embed for channels 96..127 (lanes 24..31), convergent shfl loop
        const int j0 = (lane >= 24) ? (lane - 24) * 4 : 0;
        float a0 = embed_b[j0], a1 = embed_b[j0+1], a2 = embed_b[j0+2], a3 = embed_b[j0+3];
        #pragma unroll
        for (int k = 0; k < 28; k++) {
            float hk = __shfl_sync(0xffffffffu, hval, k);
            a0 = fmaf(hk, embed_w[k*32 + j0    ], a0);
            a1 = fmaf(hk, embed_w[k*32 + j0 + 1], a1);
            a2 = fmaf(hk, embed_w[k*32 + j0 + 2], a2);
            a3 = fmaf(hk, embed_w[k*32 + j0 + 3], a3);
        }
        float v0, v1, v2, v3;
        if (lane < 24) {
            float4 xv = *(const float4*)(x + base*96 + lane*4);
            v0 = xv.x; v1 = xv.y; v2 = xv.z; v3 = xv.w;
        } else {
            v0 = tanhf(a0); v1 = tanhf(a1); v2 = tanhf(a2); v3 = tanhf(a3);
        }
        float s1 = v0+v1+v2+v3;
        float s2 = v0*v0+v1*v1+v2*v2+v3*v3;
        #pragma unroll
        for (int o = 16; o > 0; o >>= 1) {
            s1 += __shfl_xor_sync(0xffffffffu, s1, o);
            s2 += __shfl_xor_sync(0xffffffffu, s2, o);
        }
        float mu  = s1 * (1.0f/128.0f);
        float var = s2 * (1.0f/128.0f) - mu*mu;
        float rs  = rsqrtf(var + 1e-5f);
        float sv[8];
        #pragma unroll
        for (int k = 0; k < 8; k++) sv[k] = __shfl_sync(0xffffffffu, sval, k);
        const int c = lane*4;
        float o0 = loan1_b[c], o1 = loan1_b[c+1], o2 = loan1_b[c+2], o3 = loan1_b[c+3];
        #pragma unroll
        for (int k = 0; k < 8; k++) {
            o0 = fmaf(sv[k], loan1_w[k*128 + c    ], o0);
            o1 = fmaf(sv[k], loan1_w[k*128 + c + 1], o1);
            o2 = fmaf(sv[k], loan1_w[k*128 + c + 2], o2);
            o3 = fmaf(sv[k], loan1_w[k*128 + c + 3], o3);
        }
        o0 = (v0 - mu)*rs + tanhf(o0);
        o1 = (v1 - mu)*rs + tanhf(o1);
        o2 = (v2 - mu)*rs + tanhf(o2);
        o3 = (v3 - mu)*rs + tanhf(o3);
        stage4(As + m*128, (m&1)<<4, lane, o0, o1, o2, o3);
    }
    __syncthreads();

    // ---- GEMM: 5 n-tiles of 64, warps 4m x 2n ----
    const int gid = lane >> 2, tg = lane & 3;
    const int wm = warp & 3, wn = warp >> 2;

    for (int nt5 = 0; nt5 < 5; nt5++) {
        const int n_base = nt5 * 64;
        float acc[2][4][4] = {};
        #pragma unroll
        for (int it = 0; it < 8; it++) {
            const int cb = it*16 + tg*4;
            uint4 a0v[2], a8v[2], bv[4];
            #pragma unroll
            for (int mt = 0; mt < 2; mt++) {
                int r0 = wm*32 + mt*16 + gid;
                int sw = (r0 & 1) << 4;
                a0v[mt] = *(const uint4*)(As + r0*128 + (cb ^ sw));
                a8v[mt] = *(const uint4*)(As + (r0+8)*128 + (cb ^ sw));
            }
            #pragma unroll
            for (int nt = 0; nt < 4; nt++) {
                int nr = n_base + wn*32 + nt*8 + gid;
                bv[nt] = *(const uint4*)(Wp1 + nr*128 + cb);
            }
            #pragma unroll
            for (int mt = 0; mt < 2; mt++) {
                #pragma unroll
                for (int nt = 0; nt < 4; nt++) {
                    unsigned aa1[4] = {a0v[mt].x, a8v[mt].x, a0v[mt].y, a8v[mt].y};
                    unsigned bb1[2] = {bv[nt].x, bv[nt].y};
                    mma_tf32(acc[mt][nt], aa1, bb1);
                    unsigned aa2[4] = {a0v[mt].z, a8v[mt].z, a0v[mt].w, a8v[mt].w};
                    unsigned bb2[2] = {bv[nt].z, bv[nt].w};
                    mma_tf32(acc[mt][nt], aa2, bb2);
                }
            }
        }
        #pragma unroll
        for (int mt = 0; mt < 2; mt++) {
            int row = m_base + wm*32 + mt*16 + gid;
            #pragma unroll
            for (int nt = 0; nt < 4; nt++) {
                int col = n_base + wn*32 + nt*8 + tg*2;
                if (col < DPROJ) {
                    *(float2*)(S_u + (size_t)row*DPROJ + col) =
                        make_float2(acc[mt][nt][0], acc[mt][nt][1]);
                    *(float2*)(S_u + (size_t)(row+8)*DPROJ + col) =
                        make_float2(acc[mt][nt][2], acc[mt][nt][3]);
                }
            }
        }
    }
}

// ================= K2: mamba, fwd+bwd fused per u-tile =================
__global__ void __launch_bounds__(256, 3) k2_mamba(
    const float* __restrict__ cw_f, const float* __restrict__ cb_f,
    const float* __restrict__ dtb_f, const float* __restrict__ al_f,
    const float* __restrict__ Dp_f, const float* __restrict__ nw_f,
    const float* __restrict__ cw_b, const float* __restrict__ cb_b,
    const float* __restrict__ dtb_b, const float* __restrict__ al_b,
    const float* __restrict__ Dp_b, const float* __restrict__ nw_b)
{
    extern __shared__ float sm2[];
    float* u_s = sm2;                    // [30][268]
    float* xc0 = u_s + 30*268;           // [30][132]  (y overlays after scan)
    float* xc1 = xc0 + 30*132;
    float* dt0 = xc1 + 30*132;           // [30][8]
    float* dA0 = dt0 + 240;
    float* dt1 = dA0 + 240;
    float* dA1 = dt1 + 240;
    __shared__ float Aneg[2][8];

    const int s   = blockIdx.x;
    const int b   = s >> 12;
    const int tg  = (s >> 11) & 1;
    const int qg  = s & 2047;
    const int tid = threadIdx.x;
    const int dir = tid >> 7;
    const int lt  = tid & 127;

    for (int i = tid; i < 30*133; i += 256) {
        int l  = i / 133;
        int cc = i - l*133;
        int t_in = tg*3 + l/10;
        int p0   = qg*10 + (l - (l/10)*10);
        *(float2*)(u_s + l*268 + cc*2) =
            *(const float2*)(S_u + ((size_t)(b*TT + t_in)*PP + p0)*DPROJ + cc*2);
    }
    if (tid < 16) Aneg[tid>>3][tid&7] = -expf((tid < 8 ? al_f : al_b)[tid & 7]);
    __syncthreads();

    const float* conv_w = dir ? cw_b  : cw_f;
    const float* conv_b = dir ? cb_b  : cb_f;
    const float* dtbp   = dir ? dtb_b : dtb_f;
    const float* Dpp    = dir ? Dp_b  : Dp_f;
    float* xc  = dir ? xc1 : xc0;
    float* dts = dir ? dt1 : dt0;
    float* dAs = dir ? dA1 : dA0;

    for (int i = lt; i < 240; i += 128) {
        int l = i >> 3, h = i & 7;
        int lu = dir ? ((l/10)*10 + 9 - (l - (l/10)*10)) : l;
        float raw = u_s[lu*268 + 258 + h] + dtbp[h];
        float dt = (raw > 20.f) ? raw : log1pf(expf(raw));
        dts[l*8 + h] = dt;
        dAs[l*8 + h] = expf(dt * Aneg[dir][h]);
    }
    for (int c = lt; c < 130; c += 128) {
        float w0 = conv_w[c*3+0], w1 = conv_w[c*3+1], w2 = conv_w[c*3+2];
        float bias = conv_b[c];
        float p2 = 0.f, p1 = 0.f;
        #pragma unroll
        for (int l = 0; l < 30; l++) {
            int lu = dir ? ((l/10)*10 + 9 - (l - (l/10)*10)) : l;
            float v = u_s[lu*268 + 128 + c];
            float a = fmaf(p2, w0, fmaf(p1, w1, fmaf(v, w2, bias)));
            xc[l*132 + c] = a / (1.f + expf(-a));
            p2 = p1; p1 = v;
        }
    }
    __syncthreads();

    // scan: thread=channel; writes y back over xc (same [l][c] slot; safe: thread
    // c only reads cols {c,128,129} and only writes col c)
    {
        const int c = lt, h = c >> 4;
        const float Dh = Dpp[h];
        float hs = 0.f;
        #pragma unroll
        for (int l = 0; l < 30; l++) {
            int lu = dir ? ((l/10)*10 + 9 - (l - (l/10)*10)) : l;
            float xv = xc[l*132 + c];
            float Bv = xc[l*132 + 128];
            float Cv = xc[l*132 + 129];
            hs = fmaf(hs, dAs[l*8+h], dts[l*8+h]*xv*Bv);
            float y = fmaf(hs, Cv, xv*Dh);
            float z = u_s[lu*268 + c];
            y *= z / (1.f + expf(-z));
            xc[l*132 + c] = y;
        }
    }
    __syncthreads();

    const int warp = tid >> 5, lane = tid & 31;
    const int dw = warp >> 2, w4 = warp & 3;
    const float* nww = dw ? nw_b : nw_f;
    float* yss  = dw ? xc1 : xc0;
    float* ybuf = dw ? S_yb : S_yf;
    const int qgu = dw ? (2047 - qg) : qg;
    const int abase = (tg*1024 + (qgu>>1))*6 + (qgu&1);
    for (int l = w4; l < 30; l += 4) {
        float4 v = *(float4*)(yss + l*132 + lane*4);
        float ss = v.x*v.x + v.y*v.y + v.z*v.z + v.w*v.w;
        #pragma unroll
        for (int o = 16; o > 0; o >>= 1) ss += __shfl_xor_sync(0xffffffffu, ss, o);
        float scale = rsqrtf(ss*(1.f/128.f) + 1e-5f) * 0.5f;
        int l3 = l / 3;
        int f = l3*12288 + abase + (l - l3*3)*2;
        int t_out = f / PP;
        int p_out = f - t_out*PP;
        if (dw) p_out = PP-1 - p_out;
        float4 w = *(const float4*)(nww + lane*4);
        float4 o;
        o.x = v.x*scale*w.x; o.y = v.y*scale*w.y;
        o.z = v.z*scale*w.z; o.w = v.w*scale*w.w;
        *(float4*)(ybuf + ((size_t)(b*TT + t_out)*PP + p_out)*128 + lane*4) = o;
    }
}

// ===== GEMM helper: M64xN96, A in smem (stride SA, row-parity swizzle), B via LDG =====
template<int KIT, int KSTRIDE>
__device__ __forceinline__ void gemm_ldgB(const unsigned* __restrict__ Ab, int SA,
                                          const unsigned* __restrict__ Wg,
                                          int wm, int wn, int gid, int tg,
                                          float (&acc)[2][3][4])
{
    #pragma unroll
    for (int it = 0; it < KIT; it++) {
        const int cb = it*16 + tg*4;
        uint4 a0v[2], a8v[2], bv[3];
        #pragma unroll
        for (int mt = 0; mt < 2; mt++) {
            int r0 = wm*32 + mt*16 + gid;
            int sw = (r0 & 1) << 4;
            a0v[mt] = *(const uint4*)(Ab + r0*SA + (cb ^ sw));
            a8v[mt] = *(const uint4*)(Ab + (r0+8)*SA + (cb ^ sw));
        }
        #pragma unroll
        for (int nt = 0; nt < 3; nt++) {
            int nr = wn*24 + nt*8 + gid;
            bv[nt] = *(const uint4*)(Wg + nr*KSTRIDE + cb);
        }
        #pragma unroll
        for (int mt = 0; mt < 2; mt++) {
            #pragma unroll
            for (int nt = 0; nt < 3; nt++) {
                unsigned aa1[4] = {a0v[mt].x, a8v[mt].x, a0v[mt].y, a8v[mt].y};
                unsigned bb1[2] = {bv[nt].x, bv[nt].y};
                mma_tf32(acc[mt][nt], aa1, bb1);
                unsigned aa2[4] = {a0v[mt].z, a8v[mt].z, a0v[mt].w, a8v[mt].w};
                unsigned bb2[2] = {bv[nt].z, bv[nt].w};
                mma_tf32(acc[mt][nt], aa2, bb2);
            }
        }
    }
}

// ================= K34: out_proj + residual + LN + loan2 + MLP, fused =================
// BM=64, 256 threads (8 warps: 2m x 4n), B operands via LDG, 3 CTAs/SM
__global__ void __launch_bounds__(256, 3) k34_fused(
    const float* __restrict__ x,
    const int*   __restrict__ curves,
    const float* __restrict__ xstat,
    const float* __restrict__ loan2_w,
    const float* __restrict__ loan2_b,
    const float* __restrict__ b1,
    const float* __restrict__ b2,
    float* __restrict__ out)
{
    extern __shared__ unsigned smf[];
    unsigned* As  = smf;                     // [64][128]; tts/hs [64][96] overlay
    float*    x1s = (float*)(smf + 64*128);  // [64][100]
    unsigned* tts = As;
    unsigned* hs  = As;

    const int tid = threadIdx.x;
    const int m_base = blockIdx.x * 64;
    const int warp = tid >> 5, lane = tid & 31;
    const int gid = lane >> 2, tg = lane & 3;
    const int wm = warp & 1, wn = warp >> 1;

    // stage A = yf + yb
    for (int i = tid; i < 64*32; i += 256) {
        int m = i >> 5, c = i & 31;
        size_t off = (size_t)(m_base+m)*128 + c*4;
        float4 a = *(const float4*)(S_yf + off);
        float4 q = *(const float4*)(S_yb + off);
        stage4(As + m*128, (m&1)<<4, c, a.x+q.x, a.y+q.y, a.z+q.z, a.w+q.w);
    }
    __syncthreads();

    // ---- GEMM0: (yf+yb) @ Wo, K=128 ----
    float acc[2][3][4] = {};
    gemm_ldgB<8,128>(As, 128, WoP, wm, wn, gid, tg, acc);

    #pragma unroll
    for (int mt = 0; mt < 2; mt++) {
        int r = wm*32 + mt*16 + gid;
        #pragma unroll
        for (int nt = 0; nt < 3; nt++) {
            int c = wn*24 + nt*8 + tg*2;
            x1s[r*100 + c]     = acc[mt][nt][0];
            x1s[r*100 + c + 1] = acc[mt][nt][1];
            x1s[(r+8)*100 + c]     = acc[mt][nt][2];
            x1s[(r+8)*100 + c + 1] = acc[mt][nt][3];
        }
    }
    __syncthreads();   // As dead; x1s complete

    // ---- residual + LN + loan2 -> tts (overlay As) ----
    for (int r = warp; r < 64; r += 8) {
        int gm = m_base + r;
        int b  = gm / (TT*PP);
        int tp = gm - b*TT*PP;
        int t  = tp / PP;
        int p  = tp - t*PP;
        int g  = curves[b*PP + p];
        size_t xb = ((size_t)(b*TT + t)*PP + g)*96;
        float v0 = x1s[r*100 + lane*3 + 0] + x[xb + lane*3 + 0];
        float v1 = x1s[r*100 + lane*3 + 1] + x[xb + lane*3 + 1];
        float v2 = x1s[r*100 + lane*3 + 2] + x[xb + lane*3 + 2];
        x1s[r*100 + lane*3 + 0] = v0;
        x1s[r*100 + lane*3 + 1] = v1;
        x1s[r*100 + lane*3 + 2] = v2;
        float s1 = v0+v1+v2, s2 = v0*v0+v1*v1+v2*v2;
        #pragma unroll
        for (int o = 16; o > 0; o >>= 1) {
            s1 += __shfl_xor_sync(0xffffffffu, s1, o);
            s2 += __shfl_xor_sync(0xffffffffu, s2, o);
        }
        float mu  = s1 * (1.0f/96.0f);
        float var = s2 * (1.0f/96.0f) - mu*mu;
        float rs  = rsqrtf(var + 1e-5f);
        size_t sbase = ((size_t)(b*TT + t)*PP + g)*8;
        float xs[8];
        #pragma unroll
        for (int k = 0; k < 8; k++) xs[k] = xstat[sbase + k];
        int swr = (r & 1) << 4;
        #pragma unroll
        for (int i2 = 0; i2 < 3; i2++) {
            int jj = lane*3 + i2;
            float a = loan2_b[jj];
            #pragma unroll
            for (int k = 0; k < 8; k++) a = fmaf(xs[k], loan2_w[k*96 + jj], a);
            float vv = (i2 == 0) ? v0 : ((i2 == 1) ? v1 : v2);
            tts[r*96 + (kperm16(jj) ^ swr)] = f2tf32((vv - mu)*rs + tanhf(a));
        }
    }
    __syncthreads();

    // ---- GEMM1: tt @ W1, K=96 ----
    float acc1[2][3][4] = {};
    gemm_ldgB<6,96>(tts, 96, W1P, wm, wn, gid, tg, acc1);
    __syncthreads();   // all tts reads done before hs overwrite

    #pragma unroll
    for (int mt = 0; mt < 2; mt++) {
        int r = wm*32 + mt*16 + gid;
        int swr = (r & 1) << 4;
        #pragma unroll
        for (int nt = 0; nt < 3; nt++) {
            int c = wn*24 + nt*8 + tg*2;
            float bb0 = b1[c], bb1 = b1[c+1];
            hs[r*96 + (kperm16(c)   ^ swr)] = f2tf32(geluf(acc1[mt][nt][0] + bb0));
            hs[r*96 + (kperm16(c+1) ^ swr)] = f2tf32(geluf(acc1[mt][nt][1] + bb1));
            hs[(r+8)*96 + (kperm16(c)   ^ ((r&1)<<4))] = f2tf32(geluf(acc1[mt][nt][2] + bb0));
            hs[(r+8)*96 + (kperm16(c+1) ^ ((r&1)<<4))] = f2tf32(geluf(acc1[mt][nt][3] + bb1));
        }
    }
    __syncthreads();

    // ---- GEMM2: h @ W2, K=96 ----
    float acc2[2][3][4] = {};
    gemm_ldgB<6,96>(hs, 96, W2P, wm, wn, gid, tg, acc2);

    #pragma unroll
    for (int mt = 0; mt < 2; mt++) {
        int r = wm*32 + mt*16 + gid;
        int gm0 = m_base + r, gm8 = gm0 + 8;
        #pragma unroll
        for (int nt = 0; nt < 3; nt++) {
            int c = wn*24 + nt*8 + tg*2;
            float bb0 = b2[c], bb1 = b2[c+1];
            *(float2*)(out + (size_t)gm0*96 + c) = make_float2(
                acc2[mt][nt][0] + bb0 + x1s[r*100 + c],
                acc2[mt][nt][1] + bb1 + x1s[r*100 + c + 1]);
            *(float2*)(out + (size_t)gm8*96 + c) = make_float2(
                acc2[mt][nt][2] + bb0 + x1s[(r+8)*100 + c],
                acc2[mt][nt][3] + bb1 + x1s[(r+8)*100 + c + 1]);
        }
    }
}

// ================= launcher =================
extern "C" void kernel_launch(void* const* d_in, const int* in_sizes, int n_in,
                              void* d_out, int out_size)
{
    const float* x       = (const float*)d_in[0];
    const float* xstat   = (const float*)d_in[1];
    const float* xhres   = (const float*)d_in[2];
    const int*   curves  = (const int*)  d_in[3];
    const float* embed_w = (const float*)d_in[4];
    const float* embed_b = (const float*)d_in[5];
    const float* loan1_w = (const float*)d_in[6];
    const float* loan1_b = (const float*)d_in[7];
    const float* loan2_w = (const float*)d_in[8];
    const float* loan2_b = (const float*)d_in[9];
    const float* in_proj = (const float*)d_in[10];
    const float* cw_f  = (const float*)d_in[11];
    const float* cb_f  = (const float*)d_in[12];
    const float* dtb_f = (const float*)d_in[13];
    const float* al_f  = (const float*)d_in[14];
    const float* Dp_f  = (const float*)d_in[15];
    const float* nw_f  = (const float*)d_in[16];
    const float* cw_b  = (const float*)d_in[17];
    const float* cb_b  = (const float*)d_in[18];
    const float* dtb_b = (const float*)d_in[19];
    const float* al_b  = (const float*)d_in[20];
    const float* Dp_b  = (const float*)d_in[21];
    const float* nw_b  = (const float*)d_in[22];
    const float* Wo    = (const float*)d_in[23];
    const float* W1    = (const float*)d_in[24];
    const float* b1    = (const float*)d_in[25];
    const float* W2    = (const float*)d_in[26];
    const float* b2    = (const float*)d_in[27];
    float* out = (float*)d_out;

    const int smem1 = 128*128*4;                                   // 65536
    const int smem2 = (30*268 + 2*30*132 + 4*240) * 4;             // 67680
    const int smem3 = (64*128 + 64*100) * 4;                       // 58368

    cudaFuncSetAttribute(k01_inproj, cudaFuncAttributeMaxDynamicSharedMemorySize, smem1);
    cudaFuncSetAttribute(k2_mamba,   cudaFuncAttributeMaxDynamicSharedMemorySize, smem2);
    cudaFuncSetAttribute(k34_fused,  cudaFuncAttributeMaxDynamicSharedMemorySize, smem3);

    kprep<<<160, 256>>>(in_proj, Wo, W1, W2);

    k01_inproj<<<NTOK/128, 256, smem1>>>(x, xstat, xhres, curves,
                                         embed_w, embed_b, loan1_w, loan1_b);

    k2_mamba<<<8192, 256, smem2>>>(cw_f, cb_f, dtb_f, al_f, Dp_f, nw_f,
                                   cw_b, cb_b, dtb_b, al_b, Dp_b, nw_b);

    k34_fused<<<NTOK/64, 256, smem3>>>(x, curves, xstat, loan2_w, loan2_b,
                                       b1, b2, out);
}

// round 5
// speedup vs baseline: 2.6556x; 1.2404x over previous
#include <cuda_runtime.h>
#include <math.h>

#define BB 2
#define TT 6
#define PP 20480
#define NTOK (BB*TT*PP)      /* 245760 */
#define DPROJ 266

// ---------------- scratch ----------------
__device__ float S_yf[(size_t)NTOK*128];
__device__ float S_yb[(size_t)NTOK*128];
__device__ int   Goff[NTOK];        // gather base token index per output token
// pre-permuted tf32 weights (B operands, n-major, kperm16'd)
__device__ unsigned Wp1[320*128];   // in_proj (n padded 266->320)
__device__ unsigned WoP[96*128];
__device__ unsigned W1P[96*96];
__device__ unsigned W2P[96*96];

__device__ __forceinline__ float geluf(float v) {
    return 0.5f * v * (1.0f + erff(v * 0.70710678118654752f));
}
__device__ __forceinline__ unsigned f2tf32(float f) {
    unsigned r;
    asm("cvt.rna.tf32.f32 %0, %1;" : "=r"(r) : "f"(f));
    return r;
}
__device__ __forceinline__ int kperm16(int k) {
    int g = k & ~15, j = k & 15;
    return g + ((j & 3) << 2) + (j >> 2);
}
__device__ __forceinline__ void mma_tf32(float* c, const unsigned* a, const unsigned* b) {
    asm volatile(
        "mma.sync.aligned.m16n8k8.row.col.f32.tf32.tf32.f32 "
        "{%0,%1,%2,%3}, {%4,%5,%6,%7}, {%8,%9}, {%0,%1,%2,%3};"
        : "+f"(c[0]), "+f"(c[1]), "+f"(c[2]), "+f"(c[3])
        : "r"(a[0]), "r"(a[1]), "r"(a[2]), "r"(a[3]), "r"(b[0]), "r"(b[1]));
}
__device__ __forceinline__ void stage4(unsigned* row, int sw, int c, float x, float y, float z, float w) {
    int g = (c >> 2) << 4, r = c & 3;
    row[(g + r     ) ^ sw] = f2tf32(x);
    row[(g + r + 4 ) ^ sw] = f2tf32(y);
    row[(g + r + 8 ) ^ sw] = f2tf32(z);
    row[(g + r + 12) ^ sw] = f2tf32(w);
}

// ================= prep: weights + gather offsets =================
__global__ void kprep(const float* __restrict__ inproj, const float* __restrict__ Wo,
                      const float* __restrict__ W1, const float* __restrict__ W2,
                      const int* __restrict__ curves)
{
    int i = blockIdx.x * 256 + threadIdx.x;
    if (i < 320*128) {
        int n = i >> 7, k = i & 127;
        float v = (n < DPROJ) ? inproj[(size_t)k*DPROJ + n] : 0.0f;
        Wp1[n*128 + kperm16(k)] = f2tf32(v);
    }
    if (i < 96*128) {
        int n = i >> 7, k = i & 127;
        WoP[n*128 + kperm16(k)] = f2tf32(Wo[(size_t)k*96 + n]);
    }
    if (i < 96*96) {
        int n = i / 96, k = i - n*96;
        W1P[n*96 + kperm16(k)] = f2tf32(W1[(size_t)k*96 + n]);
        W2P[n*96 + kperm16(k)] = f2tf32(W2[(size_t)k*96 + n]);
    }
    if (i < NTOK) {
        int b  = i / (TT*PP);
        int tp = i - b*TT*PP;
        int t  = tp / PP;
        int p  = tp - t*PP;
        Goff[i] = (b*TT + t)*PP + curves[b*PP + p];
    }
}

// ================= K012: prologue + in_proj GEMM + mamba, fully fused =================
// CTA = (b, tg, qgrp): 60 tokens (3 t x 20 p), GEMM in smem, 2 fwd + 2 bwd scans.
// 256 threads, 2 CTAs/SM. Grid = 4096.
__global__ void __launch_bounds__(256, 2) k012_fused(
    const float* __restrict__ x,
    const float* __restrict__ xstat,
    const float* __restrict__ xhres,
    const float* __restrict__ embed_w,
    const float* __restrict__ embed_b,
    const float* __restrict__ loan1_w,
    const float* __restrict__ loan1_b,
    const float* __restrict__ cw_f, const float* __restrict__ cb_f,
    const float* __restrict__ dtb_f, const float* __restrict__ al_f,
    const float* __restrict__ Dp_f, const float* __restrict__ nw_f,
    const float* __restrict__ cw_b, const float* __restrict__ cb_b,
    const float* __restrict__ dtb_b, const float* __restrict__ al_b,
    const float* __restrict__ Dp_b, const float* __restrict__ nw_b)
{
    extern __shared__ float smx[];
    float*    u_s = smx;                     // [64][268] fp32 (rows 60..63 pad)
    float*    ovl = smx + 64*268;            // overlay: As (GEMM) then xc0/xc1
    unsigned* As  = (unsigned*)ovl;          // [64][128] swizzled tf32
    float*    dtA = smx + 64*268 + 64*128;   // dt[2][240] dA[2][240]
    __shared__ float Aneg[2][8];

    const int blk  = blockIdx.x;
    const int b    = blk >> 11;
    const int tg   = (blk >> 10) & 1;
    const int qgrp = blk & 1023;
    const int tid  = threadIdx.x;
    const int warp = tid >> 5, lane = tid & 31;

    // ---- prologue: warp-per-token, 8 passes over 64 rows (60 real) ----
    for (int pass = 0; pass < 8; pass++) {
        const int m = pass*8 + warp;
        if (m < 60) {
            const int t_loc = m / 20;
            const int p_loc = m - t_loc*20;
            const int gi = (b*TT + tg*3 + t_loc)*PP + qgrp*20 + p_loc;
            const size_t base = (size_t)Goff[gi];

            float hval = (lane < 28) ? xhres[base*28 + lane] : 0.0f;
            float sval = (lane < 8)  ? xstat[base*8 + lane]  : 0.0f;

            const int j0 = (lane >= 24) ? (lane - 24) * 4 : 0;
            float a0 = embed_b[j0], a1 = embed_b[j0+1], a2 = embed_b[j0+2], a3 = embed_b[j0+3];
            #pragma unroll
            for (int k = 0; k < 28; k++) {
                float hk = __shfl_sync(0xffffffffu, hval, k);
                a0 = fmaf(hk, embed_w[k*32 + j0    ], a0);
                a1 = fmaf(hk, embed_w[k*32 + j0 + 1], a1);
                a2 = fmaf(hk, embed_w[k*32 + j0 + 2], a2);
                a3 = fmaf(hk, embed_w[k*32 + j0 + 3], a3);
            }
            float v0, v1, v2, v3;
            if (lane < 24) {
                float4 xv = *(const float4*)(x + base*96 + lane*4);
                v0 = xv.x; v1 = xv.y; v2 = xv.z; v3 = xv.w;
            } else {
                v0 = tanhf(a0); v1 = tanhf(a1); v2 = tanhf(a2); v3 = tanhf(a3);
            }
            float s1 = v0+v1+v2+v3;
            float s2 = v0*v0+v1*v1+v2*v2+v3*v3;
            #pragma unroll
            for (int o = 16; o > 0; o >>= 1) {
                s1 += __shfl_xor_sync(0xffffffffu, s1, o);
                s2 += __shfl_xor_sync(0xffffffffu, s2, o);
            }
            float mu  = s1 * (1.0f/128.0f);
            float var = s2 * (1.0f/128.0f) - mu*mu;
            float rs  = rsqrtf(var + 1e-5f);
            float sv[8];
            #pragma unroll
            for (int k = 0; k < 8; k++) sv[k] = __shfl_sync(0xffffffffu, sval, k);
            const int c = lane*4;
            float o0 = loan1_b[c], o1 = loan1_b[c+1], o2 = loan1_b[c+2], o3 = loan1_b[c+3];
            #pragma unroll
            for (int k = 0; k < 8; k++) {
                o0 = fmaf(sv[k], loan1_w[k*128 + c    ], o0);
                o1 = fmaf(sv[k], loan1_w[k*128 + c + 1], o1);
                o2 = fmaf(sv[k], loan1_w[k*128 + c + 2], o2);
                o3 = fmaf(sv[k], loan1_w[k*128 + c + 3], o3);
            }
            o0 = (v0 - mu)*rs + tanhf(o0);
            o1 = (v1 - mu)*rs + tanhf(o1);
            o2 = (v2 - mu)*rs + tanhf(o2);
            o3 = (v3 - mu)*rs + tanhf(o3);
            stage4(As + m*128, (m&1)<<4, lane, o0, o1, o2, o3);
        } else {
            stage4(As + m*128, (m&1)<<4, lane, 0.f, 0.f, 0.f, 0.f);
        }
    }
    __syncthreads();

    // ---- GEMM: u = xn @ Wp1, M=64, N=320 (2 chunks of 160), K=128, into u_s ----
    {
        const int gid = lane >> 2, tq = lane & 3;
        const int wm = warp & 1, wn = warp >> 1;
        #pragma unroll
        for (int nc = 0; nc < 2; nc++) {
            float acc[2][5][4] = {};
            #pragma unroll
            for (int it = 0; it < 8; it++) {
                const int cb = it*16 + tq*4;
                uint4 a0v[2], a8v[2], bv[5];
                #pragma unroll
                for (int mt = 0; mt < 2; mt++) {
                    int r0 = wm*32 + mt*16 + gid;
                    int sw = (r0 & 1) << 4;
                    a0v[mt] = *(const uint4*)(As + r0*128 + (cb ^ sw));
                    a8v[mt] = *(const uint4*)(As + (r0+8)*128 + (cb ^ sw));
                }
                #pragma unroll
                for (int nt = 0; nt < 5; nt++) {
                    int nr = nc*160 + wn*40 + nt*8 + gid;
                    bv[nt] = *(const uint4*)(Wp1 + nr*128 + cb);
                }
                #pragma unroll
                for (int mt = 0; mt < 2; mt++) {
                    #pragma unroll
                    for (int nt = 0; nt < 5; nt++) {
                        unsigned aa1[4] = {a0v[mt].x, a8v[mt].x, a0v[mt].y, a8v[mt].y};
                        unsigned bb1[2] = {bv[nt].x, bv[nt].y};
                        mma_tf32(acc[mt][nt], aa1, bb1);
                        unsigned aa2[4] = {a0v[mt].z, a8v[mt].z, a0v[mt].w, a8v[mt].w};
                        unsigned bb2[2] = {bv[nt].z, bv[nt].w};
                        mma_tf32(acc[mt][nt], aa2, bb2);
                    }
                }
            }
            #pragma unroll
            for (int mt = 0; mt < 2; mt++) {
                int row = wm*32 + mt*16 + gid;
                #pragma unroll
                for (int nt = 0; nt < 5; nt++) {
                    int col = nc*160 + wn*40 + nt*8 + tq*2;
                    if (col < DPROJ) {
                        *(float2*)(u_s + row*268 + col) =
                            make_float2(acc[mt][nt][0], acc[mt][nt][1]);
                        *(float2*)(u_s + (row+8)*268 + col) =
                            make_float2(acc[mt][nt][2], acc[mt][nt][3]);
                    }
                }
            }
        }
    }
    if (tid < 16) Aneg[tid>>3][tid&7] = -expf((tid < 8 ? al_f : al_b)[tid & 7]);
    __syncthreads();   // u_s complete; As region free -> xc overlay

    // ---- mamba: 2 rounds (fwd, bwd); group g = seq (qg = qgrp*2+g) ----
    const int g  = tid >> 7;
    const int lt = tid & 127;
    float* xcg = ovl + g*3960;           // [30][132]
    float* dts = dtA + g*240;
    float* dAs = dtA + 480 + g*240;
    const int qg_src = qgrp*2 + g;

    #pragma unroll
    for (int r = 0; r < 2; r++) {
        const float* conv_w = r ? cw_b  : cw_f;
        const float* conv_b = r ? cb_b  : cb_f;
        const float* dtbp   = r ? dtb_b : dtb_f;
        const float* Dpp    = r ? Dp_b  : Dp_f;

        // dt/dA
        for (int i = lt; i < 240; i += 128) {
            int l = i >> 3, h = i & 7;
            int l10 = l / 10, lr = l - l10*10;
            int lu_r = r ? (9 - lr) : lr;
            int mu_ = l10*20 + g*10 + lu_r;
            float raw = u_s[mu_*268 + 258 + h] + dtbp[h];
            float dt = (raw > 20.f) ? raw : log1pf(expf(raw));
            dts[l*8 + h] = dt;
            dAs[l*8 + h] = expf(dt * Aneg[r][h]);
        }
        // causal depthwise conv + silu
        for (int c = lt; c < 130; c += 128) {
            float w0 = conv_w[c*3+0], w1 = conv_w[c*3+1], w2 = conv_w[c*3+2];
            float bias = conv_b[c];
            float p2 = 0.f, p1 = 0.f;
            #pragma unroll
            for (int l = 0; l < 30; l++) {
                int l10 = l / 10, lr = l - l10*10;
                int mu_ = l10*20 + g*10 + (r ? (9 - lr) : lr);
                float v = u_s[mu_*268 + 128 + c];
                float a = fmaf(p2, w0, fmaf(p1, w1, fmaf(v, w2, bias)));
                xcg[l*132 + c] = a / (1.f + expf(-a));
                p2 = p1; p1 = v;
            }
        }
        __syncthreads();

        // scalar scan; y overlays xc column c
        {
            const int c = lt, h = c >> 4;
            const float Dh = Dpp[h];
            float hs = 0.f;
            #pragma unroll
            for (int l = 0; l < 30; l++) {
                int l10 = l / 10, lr = l - l10*10;
                int mu_ = l10*20 + g*10 + (r ? (9 - lr) : lr);
                float xv = xcg[l*132 + c];
                float Bv = xcg[l*132 + 128];
                float Cv = xcg[l*132 + 129];
                hs = fmaf(hs, dAs[l*8+h], dts[l*8+h]*xv*Bv);
                float y = fmaf(hs, Cv, xv*Dh);
                float z = u_s[mu_*268 + c];
                y *= z / (1.f + expf(-z));
                xcg[l*132 + c] = y;
            }
        }
        __syncthreads();

        // RMS + scatter (4 warps per group)
        {
            const int w4 = warp & 3;
            const float* nww = r ? nw_b : nw_f;
            float* ybuf = r ? S_yb : S_yf;
            const int qgu = r ? (2047 - qg_src) : qg_src;
            const int abase = (tg*1024 + (qgu>>1))*6 + (qgu&1);
            for (int l = w4; l < 30; l += 4) {
                float4 v = *(float4*)(xcg + l*132 + lane*4);
                float ss = v.x*v.x + v.y*v.y + v.z*v.z + v.w*v.w;
                #pragma unroll
                for (int o = 16; o > 0; o >>= 1) ss += __shfl_xor_sync(0xffffffffu, ss, o);
                float scale = rsqrtf(ss*(1.f/128.f) + 1e-5f) * 0.5f;
                int l3 = l / 3;
                int f = l3*12288 + abase + (l - l3*3)*2;
                int t_out = f / PP;
                int p_out = f - t_out*PP;
                if (r) p_out = PP-1 - p_out;
                float4 w = *(const float4*)(nww + lane*4);
                float4 o;
                o.x = v.x*scale*w.x; o.y = v.y*scale*w.y;
                o.z = v.z*scale*w.z; o.w = v.w*scale*w.w;
                *(float4*)(ybuf + ((size_t)(b*TT + t_out)*PP + p_out)*128 + lane*4) = o;
            }
        }
        __syncthreads();
    }
}

// ===== GEMM helper: M64xN96, A in smem, B via LDG =====
template<int KIT, int KSTRIDE>
__device__ __forceinline__ void gemm_ldgB(const unsigned* __restrict__ Ab, int SA,
                                          const unsigned* __restrict__ Wg,
                                          int wm, int wn, int gid, int tq,
                                          float (&acc)[2][3][4])
{
    #pragma unroll
    for (int it = 0; it < KIT; it++) {
        const int cb = it*16 + tq*4;
        uint4 a0v[2], a8v[2], bv[3];
        #pragma unroll
        for (int mt = 0; mt < 2; mt++) {
            int r0 = wm*32 + mt*16 + gid;
            int sw = (r0 & 1) << 4;
            a0v[mt] = *(const uint4*)(Ab + r0*SA + (cb ^ sw));
            a8v[mt] = *(const uint4*)(Ab + (r0+8)*SA + (cb ^ sw));
        }
        #pragma unroll
        for (int nt = 0; nt < 3; nt++) {
            int nr = wn*24 + nt*8 + gid;
            bv[nt] = *(const uint4*)(Wg + nr*KSTRIDE + cb);
        }
        #pragma unroll
        for (int mt = 0; mt < 2; mt++) {
            #pragma unroll
            for (int nt = 0; nt < 3; nt++) {
                unsigned aa1[4] = {a0v[mt].x, a8v[mt].x, a0v[mt].y, a8v[mt].y};
                unsigned bb1[2] = {bv[nt].x, bv[nt].y};
                mma_tf32(acc[mt][nt], aa1, bb1);
                unsigned aa2[4] = {a0v[mt].z, a8v[mt].z, a0v[mt].w, a8v[mt].w};
                unsigned bb2[2] = {bv[nt].z, bv[nt].w};
                mma_tf32(acc[mt][nt], aa2, bb2);
            }
        }
    }
}

// ================= K34: out_proj + residual + LN + loan2 + MLP, fused =================
__global__ void __launch_bounds__(256, 3) k34_fused(
    const float* __restrict__ x,
    const float* __restrict__ xstat,
    const float* __restrict__ loan2_w,
    const float* __restrict__ loan2_b,
    const float* __restrict__ b1,
    const float* __restrict__ b2,
    float* __restrict__ out)
{
    extern __shared__ unsigned smf[];
    unsigned* As  = smf;                     // [64][128]; tts/hs overlay
    float*    x1s = (float*)(smf + 64*128);  // [64][100]
    unsigned* tts = As;
    unsigned* hs  = As;

    const int tid = threadIdx.x;
    const int m_base = blockIdx.x * 64;
    const int warp = tid >> 5, lane = tid & 31;
    const int gid = lane >> 2, tq = lane & 3;
    const int wm = warp & 1, wn = warp >> 1;

    for (int i = tid; i < 64*32; i += 256) {
        int m = i >> 5, c = i & 31;
        size_t off = (size_t)(m_base+m)*128 + c*4;
        float4 a = *(const float4*)(S_yf + off);
        float4 q = *(const float4*)(S_yb + off);
        stage4(As + m*128, (m&1)<<4, c, a.x+q.x, a.y+q.y, a.z+q.z, a.w+q.w);
    }
    __syncthreads();

    // ---- GEMM0: (yf+yb) @ Wo, K=128 ----
    float acc[2][3][4] = {};
    gemm_ldgB<8,128>(As, 128, WoP, wm, wn, gid, tq, acc);

    #pragma unroll
    for (int mt = 0; mt < 2; mt++) {
        int r = wm*32 + mt*16 + gid;
        #pragma unroll
        for (int nt = 0; nt < 3; nt++) {
            int c = wn*24 + nt*8 + tq*2;
            x1s[r*100 + c]     = acc[mt][nt][0];
            x1s[r*100 + c + 1] = acc[mt][nt][1];
            x1s[(r+8)*100 + c]     = acc[mt][nt][2];
            x1s[(r+8)*100 + c + 1] = acc[mt][nt][3];
        }
    }
    __syncthreads();

    // ---- residual + LN + loan2 -> tts ----
    for (int r = warp; r < 64; r += 8) {
        int gm = m_base + r;
        size_t base = (size_t)Goff[gm];
        size_t xb = base*96;
        float v0 = x1s[r*100 + lane*3 + 0] + x[xb + lane*3 + 0];
        float v1 = x1s[r*100 + lane*3 + 1] + x[xb + lane*3 + 1];
        float v2 = x1s[r*100 + lane*3 + 2] + x[xb + lane*3 + 2];
        x1s[r*100 + lane*3 + 0] = v0;
        x1s[r*100 + lane*3 + 1] = v1;
        x1s[r*100 + lane*3 + 2] = v2;
        float s1 = v0+v1+v2, s2 = v0*v0+v1*v1+v2*v2;
        #pragma unroll
        for (int o = 16; o > 0; o >>= 1) {
            s1 += __shfl_xor_sync(0xffffffffu, s1, o);
            s2 += __shfl_xor_sync(0xffffffffu, s2, o);
        }
        float mu  = s1 * (1.0f/96.0f);
        float var = s2 * (1.0f/96.0f) - mu*mu;
        float rs  = rsqrtf(var + 1e-5f);
        size_t sbase = base*8;
        float xs[8];
        #pragma unroll
        for (int k = 0; k < 8; k++) xs[k] = xstat[sbase + k];
        int swr = (r & 1) << 4;
        #pragma unroll
        for (int i2 = 0; i2 < 3; i2++) {
            int jj = lane*3 + i2;
            float a = loan2_b[jj];
            #pragma unroll
            for (int k = 0; k < 8; k++) a = fmaf(xs[k], loan2_w[k*96 + jj], a);
            float vv = (i2 == 0) ? v0 : ((i2 == 1) ? v1 : v2);
            tts[r*96 + (kperm16(jj) ^ swr)] = f2tf32((vv - mu)*rs + tanhf(a));
        }
    }
    __syncthreads();

    // ---- GEMM1: tt @ W1, K=96 ----
    float acc1[2][3][4] = {};
    gemm_ldgB<6,96>(tts, 96, W1P, wm, wn, gid, tq, acc1);
    __syncthreads();

    #pragma unroll
    for (int mt = 0; mt < 2; mt++) {
        int r = wm*32 + mt*16 + gid;
        int swr = (r & 1) << 4;
        #pragma unroll
        for (int nt = 0; nt < 3; nt++) {
            int c = wn*24 + nt*8 + tq*2;
            float bb0 = b1[c], bb1 = b1[c+1];
            hs[r*96 + (kperm16(c)   ^ swr)] = f2tf32(geluf(acc1[mt][nt][0] + bb0));
            hs[r*96 + (kperm16(c+1) ^ swr)] = f2tf32(geluf(acc1[mt][nt][1] + bb1));
            hs[(r+8)*96 + (kperm16(c)   ^ swr)] = f2tf32(geluf(acc1[mt][nt][2] + bb0));
            hs[(r+8)*96 + (kperm16(c+1) ^ swr)] = f2tf32(geluf(acc1[mt][nt][3] + bb1));
        }
    }
    __syncthreads();

    // ---- GEMM2: h @ W2, K=96 ----
    float acc2[2][3][4] = {};
    gemm_ldgB<6,96>(hs, 96, W2P, wm, wn, gid, tq, acc2);

    #pragma unroll
    for (int mt = 0; mt < 2; mt++) {
        int r = wm*32 + mt*16 + gid;
        int gm0 = m_base + r, gm8 = gm0 + 8;
        #pragma unroll
        for (int nt = 0; nt < 3; nt++) {
            int c = wn*24 + nt*8 + tq*2;
            float bb0 = b2[c], bb1 = b2[c+1];
            *(float2*)(out + (size_t)gm0*96 + c) = make_float2(
                acc2[mt][nt][0] + bb0 + x1s[r*100 + c],
                acc2[mt][nt][1] + bb1 + x1s[r*100 + c + 1]);
            *(float2*)(out + (size_t)gm8*96 + c) = make_float2(
                acc2[mt][nt][2] + bb0 + x1s[(r+8)*100 + c],
                acc2[mt][nt][3] + bb1 + x1s[(r+8)*100 + c + 1]);
        }
    }
}

// ================= launcher =================
extern "C" void kernel_launch(void* const* d_in, const int* in_sizes, int n_in,
                              void* d_out, int out_size)
{
    const float* x       = (const float*)d_in[0];
    const float* xstat   = (const float*)d_in[1];
    const float* xhres   = (const float*)d_in[2];
    const int*   curves  = (const int*)  d_in[3];
    const float* embed_w = (const float*)d_in[4];
    const float* embed_b = (const float*)d_in[5];
    const float* loan1_w = (const float*)d_in[6];
    const float* loan1_b = (const float*)d_in[7];
    const float* loan2_w = (const float*)d_in[8];
    const float* loan2_b = (const float*)d_in[9];
    const float* in_proj = (const float*)d_in[10];
    const float* cw_f  = (const float*)d_in[11];
    const float* cb_f  = (const float*)d_in[12];
    const float* dtb_f = (const float*)d_in[13];
    const float* al_f  = (const float*)d_in[14];
    const float* Dp_f  = (const float*)d_in[15];
    const float* nw_f  = (const float*)d_in[16];
    const float* cw_b  = (const float*)d_in[17];
    const float* cb_b  = (const float*)d_in[18];
    const float* dtb_b = (const float*)d_in[19];
    const float* al_b  = (const float*)d_in[20];
    const float* Dp_b  = (const float*)d_in[21];
    const float* nw_b  = (const float*)d_in[22];
    const float* Wo    = (const float*)d_in[23];
    const float* W1    = (const float*)d_in[24];
    const float* b1    = (const float*)d_in[25];
    const float* W2    = (const float*)d_in[26];
    const float* b2    = (const float*)d_in[27];
    float* out = (float*)d_out;

    const int smem012 = (64*268 + 64*128 + 960) * 4;   // 105216
    const int smem34  = (64*128 + 64*100) * 4;         // 58368

    cudaFuncSetAttribute(k012_fused, cudaFuncAttributeMaxDynamicSharedMemorySize, smem012);
    cudaFuncSetAttribute(k34_fused,  cudaFuncAttributeMaxDynamicSharedMemorySize, smem34);

    kprep<<<NTOK/256, 256>>>(in_proj, Wo, W1, W2, curves);

    k012_fused<<<4096, 256, smem012>>>(x, xstat, xhres,
                                       embed_w, embed_b, loan1_w, loan1_b,
                                       cw_f, cb_f, dtb_f, al_f, Dp_f, nw_f,
                                       cw_b, cb_b, dtb_b, al_b, Dp_b, nw_b);

    k34_fused<<<NTOK/64, 256, smem34>>>(x, xstat, loan2_w, loan2_b, b1, b2, out);
}